// round 1
// baseline (speedup 1.0000x reference)
#include <cuda_runtime.h>

#define EPSV 1e-5f

// ---------------- scratch (static device arrays; no allocation) ----------------
__device__ float g_Wp[768 * 256];          // BN-folded QKV weight
__device__ float g_bp[768];                // BN-folded QKV bias
__device__ float g_qkv[16 * 768 * 1024];   // QKV activations  [b][o][p]
__device__ float g_av[16 * 256 * 1024];    // attention output [b][c][p]

// ---------------- kernel A: fold BN into QKV weights ----------------
__global__ void fold_k(const float* __restrict__ qkv_w, const float* __restrict__ qkv_b,
                       const float* __restrict__ gamma, const float* __restrict__ beta,
                       const float* __restrict__ mean,  const float* __restrict__ var) {
    int o = blockIdx.x;          // 0..767
    int c = threadIdx.x;         // 0..255
    float sc = gamma[c] * rsqrtf(var[c] + EPSV);
    float sh = beta[c] - mean[c] * sc;
    float w = qkv_w[o * 256 + c];
    g_Wp[o * 256 + c] = w * sc;
    float part = w * sh;
    __shared__ float red[8];
    #pragma unroll
    for (int m = 16; m > 0; m >>= 1) part += __shfl_xor_sync(0xffffffffu, part, m);
    if ((c & 31) == 0) red[c >> 5] = part;
    __syncthreads();
    if (c < 8) {
        float v = red[c];
        #pragma unroll
        for (int m = 4; m > 0; m >>= 1) v += __shfl_xor_sync(0xffu, v, m);
        if (c == 0) g_bp[o] = qkv_b[o] + v;
    }
}

// ---------------- tiled GEMM:  Y[b][o][p] = W[o][:] . X[b][:][p] + bias[o] (+resid) ----
// grid: (N/128, M/128, B), block 256.  K multiple of 16. N = 1024.
__global__ void gemm_k(const float* __restrict__ W, const float* __restrict__ bias,
                       const float* __restrict__ X, float* __restrict__ Y,
                       const float* __restrict__ resid, int M, int K) {
    const int N = 1024;
    int pbase = blockIdx.x * 128;
    int obase = blockIdx.y * 128;
    int b = blockIdx.z;
    int tid = threadIdx.x;
    int tx = tid & 15, ty = tid >> 4;

    __shared__ float Ws[128 * 17];
    __shared__ float Xs[16 * 128];

    float acc[8][8];
    #pragma unroll
    for (int i = 0; i < 8; i++)
        #pragma unroll
        for (int j = 0; j < 8; j++) acc[i][j] = 0.f;

    const float* Xb = X + (size_t)b * K * N;

    for (int kc = 0; kc < K; kc += 16) {
        #pragma unroll 4
        for (int idx = tid; idx < 128 * 16; idx += 256) {
            int o = idx >> 4, kk = idx & 15;
            Ws[o * 17 + kk] = W[(size_t)(obase + o) * K + kc + kk];
        }
        #pragma unroll 4
        for (int idx = tid; idx < 16 * 128; idx += 256) {
            int kk = idx >> 7, p = idx & 127;
            Xs[kk * 128 + p] = Xb[(size_t)(kc + kk) * N + pbase + p];
        }
        __syncthreads();
        #pragma unroll
        for (int kk = 0; kk < 16; kk++) {
            float a[8];
            #pragma unroll
            for (int i = 0; i < 8; i++) a[i] = Ws[(ty * 8 + i) * 17 + kk];
            float4 b0 = *(const float4*)&Xs[kk * 128 + tx * 8];
            float4 b1 = *(const float4*)&Xs[kk * 128 + tx * 8 + 4];
            float bb[8] = {b0.x, b0.y, b0.z, b0.w, b1.x, b1.y, b1.z, b1.w};
            #pragma unroll
            for (int i = 0; i < 8; i++)
                #pragma unroll
                for (int j = 0; j < 8; j++) acc[i][j] = fmaf(a[i], bb[j], acc[i][j]);
        }
        __syncthreads();
    }

    #pragma unroll
    for (int i = 0; i < 8; i++) {
        int o = obase + ty * 8 + i;
        float bv = bias[o];
        size_t base = ((size_t)b * M + o) * N + pbase + tx * 8;
        if (resid) {
            #pragma unroll
            for (int j = 0; j < 8; j++) Y[base + j] = acc[i][j] + bv + resid[base + j];
        } else {
            #pragma unroll
            for (int j = 0; j < 8; j++) Y[base + j] = acc[i][j] + bv;
        }
    }
}

// ---------------- kernel C: fused flash attention ----------------
// qkv layout: [b][head*192 + {q:0..63, k:64..127, v:128..191}][p]
// grid: (8 qtiles, 4 heads, 16 batch), block 256.
#define FL_SMEM_FLOATS (64*128 + 64*128 + 128*68 + 128*129 + 4*128)
__global__ void flash_k(const float* __restrict__ qkv, float* __restrict__ av) {
    extern __shared__ float sm[];
    float* Qs = sm;                       // [c][q]  64x128
    float* Ks = Qs + 64 * 128;            // [c][k]  64x128
    float* Vt = Ks + 64 * 128;            // [k][c]  128x68 (pad)
    float* Ps = Vt + 128 * 68;            // [q][k]  128x129 (pad)
    float* m_s  = Ps + 128 * 129;
    float* l_s  = m_s + 128;
    float* al_s = l_s + 128;
    float* tm_s = al_s + 128;

    int qb = blockIdx.x * 128;
    int h  = blockIdx.y;
    int b  = blockIdx.z;
    int tid = threadIdx.x;
    int tx = tid & 15, ty = tid >> 4;

    const size_t hb = ((size_t)b * 768 + (size_t)h * 192) * 1024;
    const float* Qg = qkv + hb;
    const float* Kg = qkv + hb + 64 * 1024;
    const float* Vg = qkv + hb + 128 * 1024;

    // load Q tile, scaled by 1/sqrt(C)=1/16
    for (int idx = tid; idx < 64 * 128; idx += 256) {
        int c = idx >> 7, q = idx & 127;
        Qs[c * 128 + q] = Qg[(size_t)c * 1024 + qb + q] * 0.0625f;
    }
    if (tid < 128) { m_s[tid] = -1e30f; l_s[tid] = 0.f; }

    float oa[8][4];
    #pragma unroll
    for (int i = 0; i < 8; i++)
        #pragma unroll
        for (int j = 0; j < 4; j++) oa[i][j] = 0.f;

    for (int kt = 0; kt < 8; kt++) {
        __syncthreads();   // previous tile consumers done (also covers Q load / init)
        for (int idx = tid; idx < 64 * 128; idx += 256) {
            int c = idx >> 7, k = idx & 127;
            float kv = Kg[(size_t)c * 1024 + kt * 128 + k];
            float vv = Vg[(size_t)c * 1024 + kt * 128 + k];
            Ks[c * 128 + k] = kv;
            Vt[k * 68 + c]  = vv;
        }
        __syncthreads();

        // ---- S = (Q/16)^T K :  thread tile 8q x 8k ----
        float s[8][8];
        #pragma unroll
        for (int i = 0; i < 8; i++)
            #pragma unroll
            for (int j = 0; j < 8; j++) s[i][j] = 0.f;

        #pragma unroll 2
        for (int c = 0; c < 64; c++) {
            float4 qa0 = *(const float4*)&Qs[c * 128 + ty * 8];
            float4 qa1 = *(const float4*)&Qs[c * 128 + ty * 8 + 4];
            float4 kb0 = *(const float4*)&Ks[c * 128 + tx * 8];
            float4 kb1 = *(const float4*)&Ks[c * 128 + tx * 8 + 4];
            float qa[8] = {qa0.x, qa0.y, qa0.z, qa0.w, qa1.x, qa1.y, qa1.z, qa1.w};
            float kb[8] = {kb0.x, kb0.y, kb0.z, kb0.w, kb1.x, kb1.y, kb1.z, kb1.w};
            #pragma unroll
            for (int i = 0; i < 8; i++)
                #pragma unroll
                for (int j = 0; j < 8; j++) s[i][j] = fmaf(qa[i], kb[j], s[i][j]);
        }

        // ---- row max across the 16 tx lanes ----
        #pragma unroll
        for (int i = 0; i < 8; i++) {
            float r = s[i][0];
            #pragma unroll
            for (int j = 1; j < 8; j++) r = fmaxf(r, s[i][j]);
            r = fmaxf(r, __shfl_xor_sync(0xffffffffu, r, 1));
            r = fmaxf(r, __shfl_xor_sync(0xffffffffu, r, 2));
            r = fmaxf(r, __shfl_xor_sync(0xffffffffu, r, 4));
            r = fmaxf(r, __shfl_xor_sync(0xffffffffu, r, 8));
            if (tx == 0) tm_s[ty * 8 + i] = r;
        }
        __syncthreads();
        if (tid < 128) {
            float mo = m_s[tid];
            float mn = fmaxf(mo, tm_s[tid]);
            float a = __expf(mo - mn);
            m_s[tid] = mn; al_s[tid] = a; l_s[tid] *= a;
        }
        __syncthreads();

        // ---- P = exp(S - m), store to smem, accumulate row sums ----
        #pragma unroll
        for (int i = 0; i < 8; i++) {
            int q = ty * 8 + i;
            float mq = m_s[q];
            float rs = 0.f;
            #pragma unroll
            for (int j = 0; j < 8; j++) {
                float p = __expf(s[i][j] - mq);
                Ps[q * 129 + tx * 8 + j] = p;
                rs += p;
            }
            rs += __shfl_xor_sync(0xffffffffu, rs, 1);
            rs += __shfl_xor_sync(0xffffffffu, rs, 2);
            rs += __shfl_xor_sync(0xffffffffu, rs, 4);
            rs += __shfl_xor_sync(0xffffffffu, rs, 8);
            if (tx == 0) l_s[q] += rs;
        }
        __syncthreads();

        // ---- O += P V^T : thread owns 8 queries (stride 16: q = i*16+ty), 4 channels (tx*4) ----
        float al[8];
        #pragma unroll
        for (int i = 0; i < 8; i++) al[i] = al_s[i * 16 + ty];
        #pragma unroll
        for (int i = 0; i < 8; i++) {
            oa[i][0] *= al[i]; oa[i][1] *= al[i];
            oa[i][2] *= al[i]; oa[i][3] *= al[i];
        }
        #pragma unroll 2
        for (int k = 0; k < 128; k++) {
            float4 v = *(const float4*)&Vt[k * 68 + tx * 4];
            #pragma unroll
            for (int i = 0; i < 8; i++) {
                float p = Ps[(i * 16 + ty) * 129 + k];
                oa[i][0] = fmaf(p, v.x, oa[i][0]);
                oa[i][1] = fmaf(p, v.y, oa[i][1]);
                oa[i][2] = fmaf(p, v.z, oa[i][2]);
                oa[i][3] = fmaf(p, v.w, oa[i][3]);
            }
        }
    }
    __syncthreads();

    // ---- finalize: O /= l, stage [c][q] in smem, coalesced store ----
    #pragma unroll
    for (int i = 0; i < 8; i++) {
        int q = i * 16 + ty;
        float inv = 1.f / l_s[q];
        #pragma unroll
        for (int j = 0; j < 4; j++)
            Ps[(tx * 4 + j) * 128 + q] = oa[i][j] * inv;
    }
    __syncthreads();
    size_t ob = ((size_t)b * 256 + (size_t)h * 64) * 1024 + qb;
    for (int idx = tid; idx < 64 * 128; idx += 256) {
        int c = idx >> 7, q = idx & 127;
        av[ob + (size_t)c * 1024 + q] = Ps[c * 128 + q];
    }
}

// ---------------- launcher ----------------
extern "C" void kernel_launch(void* const* d_in, const int* in_sizes, int n_in,
                              void* d_out, int out_size) {
    const float* x      = (const float*)d_in[0];
    const float* gamma  = (const float*)d_in[1];
    const float* beta   = (const float*)d_in[2];
    const float* rmean  = (const float*)d_in[3];
    const float* rvar   = (const float*)d_in[4];
    const float* qkv_w  = (const float*)d_in[5];
    const float* qkv_b  = (const float*)d_in[6];
    const float* out_w  = (const float*)d_in[7];
    const float* out_b  = (const float*)d_in[8];

    float *Wp, *bp, *qkvbuf, *avbuf;
    cudaGetSymbolAddress((void**)&Wp,     g_Wp);
    cudaGetSymbolAddress((void**)&bp,     g_bp);
    cudaGetSymbolAddress((void**)&qkvbuf, g_qkv);
    cudaGetSymbolAddress((void**)&avbuf,  g_av);

    // A: fold BN into QKV weights
    fold_k<<<768, 256>>>(qkv_w, qkv_b, gamma, beta, rmean, rvar);

    // B: QKV = W' x + b'
    gemm_k<<<dim3(8, 6, 16), 256>>>(Wp, bp, x, qkvbuf, nullptr, 768, 256);

    // C: fused attention
    size_t smem = FL_SMEM_FLOATS * sizeof(float);
    cudaFuncSetAttribute(flash_k, cudaFuncAttributeMaxDynamicSharedMemorySize, (int)smem);
    flash_k<<<dim3(8, 4, 16), 256, smem>>>(qkvbuf, avbuf);

    // D: out = x + out_w @ av + out_b
    gemm_k<<<dim3(8, 2, 16), 256>>>(out_w, out_b, avbuf, (float*)d_out, x, 256, 256);
}

// round 2
// speedup vs baseline: 1.8074x; 1.8074x over previous
#include <cuda_runtime.h>

#define EPSV 1e-5f

// ---------------- scratch (static device arrays; no allocation) ----------------
__device__ float g_Wp[768 * 256];          // BN-folded QKV weight
__device__ float g_bp[768];                // BN-folded QKV bias
__device__ float g_qkv[16 * 768 * 1024];   // QKV activations  [b][o][p]
__device__ float g_av[16 * 256 * 1024];    // attention output [b][c][p]

// ---------------- kernel A: fold BN into QKV weights ----------------
__global__ void fold_k(const float* __restrict__ qkv_w, const float* __restrict__ qkv_b,
                       const float* __restrict__ gamma, const float* __restrict__ beta,
                       const float* __restrict__ mean,  const float* __restrict__ var) {
    int o = blockIdx.x;          // 0..767
    int c = threadIdx.x;         // 0..255
    float sc = gamma[c] * rsqrtf(var[c] + EPSV);
    float sh = beta[c] - mean[c] * sc;
    float w = qkv_w[o * 256 + c];
    g_Wp[o * 256 + c] = w * sc;
    float part = w * sh;
    __shared__ float red[8];
    #pragma unroll
    for (int m = 16; m > 0; m >>= 1) part += __shfl_xor_sync(0xffffffffu, part, m);
    if ((c & 31) == 0) red[c >> 5] = part;
    __syncthreads();
    if (c < 8) {
        float v = red[c];
        #pragma unroll
        for (int m = 4; m > 0; m >>= 1) v += __shfl_xor_sync(0xffu, v, m);
        if (c == 0) g_bp[o] = qkv_b[o] + v;
    }
}

// ---------------- tiled GEMM:  Y[b][o][p] = W[o][:] . X[b][:][p] + bias[o] (+resid) ----
__global__ void gemm_k(const float* __restrict__ W, const float* __restrict__ bias,
                       const float* __restrict__ X, float* __restrict__ Y,
                       const float* __restrict__ resid, int M, int K) {
    const int N = 1024;
    int pbase = blockIdx.x * 128;
    int obase = blockIdx.y * 128;
    int b = blockIdx.z;
    int tid = threadIdx.x;
    int tx = tid & 15, ty = tid >> 4;

    __shared__ float Ws[128 * 17];
    __shared__ float Xs[16 * 128];

    float acc[8][8];
    #pragma unroll
    for (int i = 0; i < 8; i++)
        #pragma unroll
        for (int j = 0; j < 8; j++) acc[i][j] = 0.f;

    const float* Xb = X + (size_t)b * K * N;

    for (int kc = 0; kc < K; kc += 16) {
        #pragma unroll 4
        for (int idx = tid; idx < 128 * 16; idx += 256) {
            int o = idx >> 4, kk = idx & 15;
            Ws[o * 17 + kk] = W[(size_t)(obase + o) * K + kc + kk];
        }
        #pragma unroll 4
        for (int idx = tid; idx < 16 * 128; idx += 256) {
            int kk = idx >> 7, p = idx & 127;
            Xs[kk * 128 + p] = Xb[(size_t)(kc + kk) * N + pbase + p];
        }
        __syncthreads();
        #pragma unroll
        for (int kk = 0; kk < 16; kk++) {
            float a[8];
            #pragma unroll
            for (int i = 0; i < 8; i++) a[i] = Ws[(ty * 8 + i) * 17 + kk];
            float4 b0 = *(const float4*)&Xs[kk * 128 + tx * 8];
            float4 b1 = *(const float4*)&Xs[kk * 128 + tx * 8 + 4];
            float bb[8] = {b0.x, b0.y, b0.z, b0.w, b1.x, b1.y, b1.z, b1.w};
            #pragma unroll
            for (int i = 0; i < 8; i++)
                #pragma unroll
                for (int j = 0; j < 8; j++) acc[i][j] = fmaf(a[i], bb[j], acc[i][j]);
        }
        __syncthreads();
    }

    #pragma unroll
    for (int i = 0; i < 8; i++) {
        int o = obase + ty * 8 + i;
        float bv = bias[o];
        size_t base = ((size_t)b * M + o) * N + pbase + tx * 8;
        if (resid) {
            #pragma unroll
            for (int j = 0; j < 8; j++) Y[base + j] = acc[i][j] + bv + resid[base + j];
        } else {
            #pragma unroll
            for (int j = 0; j < 8; j++) Y[base + j] = acc[i][j] + bv;
        }
    }
}

// ---------------- helpers for tf32 mma ----------------
__device__ __forceinline__ unsigned f2tf32(float f) {
    unsigned r; asm("cvt.rna.tf32.f32 %0, %1;" : "=r"(r) : "f"(f)); return r;
}
__device__ __forceinline__ void mma_tf32(float c[4],
                                         unsigned a0, unsigned a1, unsigned a2, unsigned a3,
                                         unsigned b0, unsigned b1) {
    asm volatile("mma.sync.aligned.m16n8k8.row.col.f32.tf32.tf32.f32 "
                 "{%0,%1,%2,%3}, {%4,%5,%6,%7}, {%8,%9}, {%0,%1,%2,%3};"
                 : "+f"(c[0]), "+f"(c[1]), "+f"(c[2]), "+f"(c[3])
                 : "r"(a0), "r"(a1), "r"(a2), "r"(a3), "r"(b0), "r"(b1));
}

// ---------------- kernel C: fused flash attention (tf32 tensor cores) ----------------
// qkv layout: [b][head*192 + {q:0..63, k:64..127, v:128..191}][p]
// grid: (8 qtiles, 4 heads, 16 batch), block 256 (8 warps).
// Warp w owns query rows [w*16, w*16+16). K processed in 16 tiles of 64.
// smem floats: Qs 128x68 (q-major, tf32) reused as Os 64x132; Ks 64x68 [k][c];
//              Vs 64x72 [k][c]; Ps per-warp 16x76.
#define FL_QS   (128 * 68)
#define FL_KS   (64 * 68)
#define FL_VS   (64 * 72)
#define FL_PS   (8 * 16 * 76)
#define FL_SMEM_FLOATS (FL_QS + FL_KS + FL_VS + FL_PS)

__global__ void __launch_bounds__(256, 2) flash_k(const float* __restrict__ qkv,
                                                  float* __restrict__ av) {
    extern __shared__ float sm[];
    float* Qs = sm;
    float* Ks = Qs + FL_QS;
    float* Vs = Ks + FL_KS;
    float* Ps = Vs + FL_VS;

    int tid = threadIdx.x;
    int w = tid >> 5, lane = tid & 31;
    int r = lane >> 2, ql = lane & 3;
    int qb = blockIdx.x * 128;
    int h  = blockIdx.y;
    int b  = blockIdx.z;

    const size_t hb = ((size_t)b * 768 + (size_t)h * 192) * 1024;
    const float* Qg = qkv + hb;
    const float* Kg = qkv + hb + 64 * 1024;
    const float* Vg = qkv + hb + 128 * 1024;
    const float QSC = 0.0625f * 1.44269504088896340736f;  // 1/sqrt(256) * log2(e)

    // load Q tile -> Qs[q][c], scaled, tf32
    for (int idx = tid; idx < 128 * 64; idx += 256) {
        int c = idx >> 7, q = idx & 127;
        Qs[q * 68 + c] = __uint_as_float(f2tf32(Qg[(size_t)c * 1024 + qb + q] * QSC));
    }

    float m0 = -1e30f, m1 = -1e30f, l0 = 0.f, l1 = 0.f;
    float O[8][4];
    #pragma unroll
    for (int nb = 0; nb < 8; nb++)
        #pragma unroll
        for (int j = 0; j < 4; j++) O[nb][j] = 0.f;

    float* Pw = Ps + w * 16 * 76;
    const int qrow = w * 16;

    for (int kt = 0; kt < 16; kt++) {
        __syncthreads();
        int kbase = kt * 64;
        for (int idx = tid; idx < 64 * 64; idx += 256) {
            int c = idx >> 6, k = idx & 63;
            Ks[k * 68 + c] = __uint_as_float(f2tf32(Kg[(size_t)c * 1024 + kbase + k]));
            Vs[k * 72 + c] = __uint_as_float(f2tf32(Vg[(size_t)c * 1024 + kbase + k]));
        }
        __syncthreads();

        // ---- S = Q K^T for this warp's 16 rows x 64 cols ----
        float S[8][4];
        #pragma unroll
        for (int nb = 0; nb < 8; nb++)
            #pragma unroll
            for (int j = 0; j < 4; j++) S[nb][j] = 0.f;

        #pragma unroll
        for (int kk = 0; kk < 8; kk++) {
            unsigned qa0 = __float_as_uint(Qs[(qrow + r) * 68 + kk * 8 + ql]);
            unsigned qa1 = __float_as_uint(Qs[(qrow + r + 8) * 68 + kk * 8 + ql]);
            unsigned qa2 = __float_as_uint(Qs[(qrow + r) * 68 + kk * 8 + ql + 4]);
            unsigned qa3 = __float_as_uint(Qs[(qrow + r + 8) * 68 + kk * 8 + ql + 4]);
            #pragma unroll
            for (int nb = 0; nb < 8; nb++) {
                unsigned b0 = __float_as_uint(Ks[(nb * 8 + r) * 68 + kk * 8 + ql]);
                unsigned b1 = __float_as_uint(Ks[(nb * 8 + r) * 68 + kk * 8 + ql + 4]);
                mma_tf32(S[nb], qa0, qa1, qa2, qa3, b0, b1);
            }
        }

        // ---- online softmax (rows r and r+8; quad lanes share a row) ----
        float mx0 = -1e30f, mx1 = -1e30f;
        #pragma unroll
        for (int nb = 0; nb < 8; nb++) {
            mx0 = fmaxf(mx0, fmaxf(S[nb][0], S[nb][1]));
            mx1 = fmaxf(mx1, fmaxf(S[nb][2], S[nb][3]));
        }
        mx0 = fmaxf(mx0, __shfl_xor_sync(0xffffffffu, mx0, 1));
        mx0 = fmaxf(mx0, __shfl_xor_sync(0xffffffffu, mx0, 2));
        mx1 = fmaxf(mx1, __shfl_xor_sync(0xffffffffu, mx1, 1));
        mx1 = fmaxf(mx1, __shfl_xor_sync(0xffffffffu, mx1, 2));

        float mn0 = fmaxf(m0, mx0), mn1 = fmaxf(m1, mx1);
        float al0 = exp2f(m0 - mn0), al1 = exp2f(m1 - mn1);
        m0 = mn0; m1 = mn1;

        float rs0 = 0.f, rs1 = 0.f;
        #pragma unroll
        for (int nb = 0; nb < 8; nb++) {
            float p0 = exp2f(S[nb][0] - mn0);
            float p1 = exp2f(S[nb][1] - mn0);
            float p2 = exp2f(S[nb][2] - mn1);
            float p3 = exp2f(S[nb][3] - mn1);
            rs0 += p0 + p1; rs1 += p2 + p3;
            Pw[r * 76 + nb * 8 + 2 * ql]           = __uint_as_float(f2tf32(p0));
            Pw[r * 76 + nb * 8 + 2 * ql + 1]       = __uint_as_float(f2tf32(p1));
            Pw[(r + 8) * 76 + nb * 8 + 2 * ql]     = __uint_as_float(f2tf32(p2));
            Pw[(r + 8) * 76 + nb * 8 + 2 * ql + 1] = __uint_as_float(f2tf32(p3));
        }
        rs0 += __shfl_xor_sync(0xffffffffu, rs0, 1);
        rs0 += __shfl_xor_sync(0xffffffffu, rs0, 2);
        rs1 += __shfl_xor_sync(0xffffffffu, rs1, 1);
        rs1 += __shfl_xor_sync(0xffffffffu, rs1, 2);
        l0 = l0 * al0 + rs0;
        l1 = l1 * al1 + rs1;

        #pragma unroll
        for (int nb = 0; nb < 8; nb++) {
            O[nb][0] *= al0; O[nb][1] *= al0;
            O[nb][2] *= al1; O[nb][3] *= al1;
        }
        __syncwarp();

        // ---- O += P V ----
        #pragma unroll
        for (int kk = 0; kk < 8; kk++) {
            unsigned a0 = __float_as_uint(Pw[r * 76 + kk * 8 + ql]);
            unsigned a1 = __float_as_uint(Pw[(r + 8) * 76 + kk * 8 + ql]);
            unsigned a2 = __float_as_uint(Pw[r * 76 + kk * 8 + ql + 4]);
            unsigned a3 = __float_as_uint(Pw[(r + 8) * 76 + kk * 8 + ql + 4]);
            #pragma unroll
            for (int nb = 0; nb < 8; nb++) {
                unsigned b0 = __float_as_uint(Vs[(kk * 8 + ql) * 72 + nb * 8 + r]);
                unsigned b1 = __float_as_uint(Vs[(kk * 8 + ql + 4) * 72 + nb * 8 + r]);
                mma_tf32(O[nb], a0, a1, a2, a3, b0, b1);
            }
        }
    }
    __syncthreads();   // everyone done reading Qs before reuse as output staging

    float inv0 = 1.f / l0, inv1 = 1.f / l1;
    #pragma unroll
    for (int nb = 0; nb < 8; nb++) {
        int c = nb * 8 + 2 * ql;
        int q = qrow + r;
        Qs[c * 132 + q]           = O[nb][0] * inv0;
        Qs[(c + 1) * 132 + q]     = O[nb][1] * inv0;
        Qs[c * 132 + q + 8]       = O[nb][2] * inv1;
        Qs[(c + 1) * 132 + q + 8] = O[nb][3] * inv1;
    }
    __syncthreads();

    size_t ob = ((size_t)b * 256 + (size_t)h * 64) * 1024 + qb;
    for (int idx = tid; idx < 64 * 128; idx += 256) {
        int c = idx >> 7, q = idx & 127;
        av[ob + (size_t)c * 1024 + q] = Qs[c * 132 + q];
    }
}

// ---------------- launcher ----------------
extern "C" void kernel_launch(void* const* d_in, const int* in_sizes, int n_in,
                              void* d_out, int out_size) {
    const float* x      = (const float*)d_in[0];
    const float* gamma  = (const float*)d_in[1];
    const float* beta   = (const float*)d_in[2];
    const float* rmean  = (const float*)d_in[3];
    const float* rvar   = (const float*)d_in[4];
    const float* qkv_w  = (const float*)d_in[5];
    const float* qkv_b  = (const float*)d_in[6];
    const float* out_w  = (const float*)d_in[7];
    const float* out_b  = (const float*)d_in[8];

    float *Wp, *bp, *qkvbuf, *avbuf;
    cudaGetSymbolAddress((void**)&Wp,     g_Wp);
    cudaGetSymbolAddress((void**)&bp,     g_bp);
    cudaGetSymbolAddress((void**)&qkvbuf, g_qkv);
    cudaGetSymbolAddress((void**)&avbuf,  g_av);

    // A: fold BN into QKV weights
    fold_k<<<768, 256>>>(qkv_w, qkv_b, gamma, beta, rmean, rvar);

    // B: QKV = W' x + b'
    gemm_k<<<dim3(8, 6, 16), 256>>>(Wp, bp, x, qkvbuf, nullptr, 768, 256);

    // C: fused attention (tf32 tensor cores)
    size_t smem = FL_SMEM_FLOATS * sizeof(float);
    cudaFuncSetAttribute(flash_k, cudaFuncAttributeMaxDynamicSharedMemorySize, (int)smem);
    flash_k<<<dim3(8, 4, 16), 256, smem>>>(qkvbuf, avbuf);

    // D: out = x + out_w @ av + out_b
    gemm_k<<<dim3(8, 2, 16), 256>>>(out_w, out_b, avbuf, (float*)d_out, x, 256, 256);
}

// round 3
// speedup vs baseline: 2.3827x; 1.3183x over previous
#include <cuda_runtime.h>

#define EPSV 1e-5f

// ---------------- scratch (static device arrays; no allocation) ----------------
__device__ float g_Wp[768 * 256];          // BN-folded QKV weight
__device__ float g_bp[768];                // BN-folded QKV bias
__device__ float g_qkv[16 * 768 * 1024];   // QKV activations  [b][o][p]
__device__ float g_av[16 * 256 * 1024];    // attention output [b][c][p]

// ---------------- helpers ----------------
__device__ __forceinline__ unsigned f2tf32(float f) {
    unsigned r; asm("cvt.rna.tf32.f32 %0, %1;" : "=r"(r) : "f"(f)); return r;
}
__device__ __forceinline__ float ftf32(float f) {
    return __uint_as_float(f2tf32(f));
}
__device__ __forceinline__ float fexp2(float x) {
    float r; asm("ex2.approx.ftz.f32 %0, %1;" : "=f"(r) : "f"(x)); return r;
}
__device__ __forceinline__ void mma_tf32(float c[4],
                                         const unsigned a[4],
                                         unsigned b0, unsigned b1) {
    asm volatile("mma.sync.aligned.m16n8k8.row.col.f32.tf32.tf32.f32 "
                 "{%0,%1,%2,%3}, {%4,%5,%6,%7}, {%8,%9}, {%0,%1,%2,%3};"
                 : "+f"(c[0]), "+f"(c[1]), "+f"(c[2]), "+f"(c[3])
                 : "r"(a[0]), "r"(a[1]), "r"(a[2]), "r"(a[3]), "r"(b0), "r"(b1));
}

// ---------------- kernel A: fold BN into QKV weights ----------------
__global__ void fold_k(const float* __restrict__ qkv_w, const float* __restrict__ qkv_b,
                       const float* __restrict__ gamma, const float* __restrict__ beta,
                       const float* __restrict__ mean,  const float* __restrict__ var) {
    int o = blockIdx.x;          // 0..767
    int c = threadIdx.x;         // 0..255
    float sc = gamma[c] * rsqrtf(var[c] + EPSV);
    float sh = beta[c] - mean[c] * sc;
    float w = qkv_w[o * 256 + c];
    g_Wp[o * 256 + c] = w * sc;
    float part = w * sh;
    __shared__ float red[8];
    #pragma unroll
    for (int m = 16; m > 0; m >>= 1) part += __shfl_xor_sync(0xffffffffu, part, m);
    if ((c & 31) == 0) red[c >> 5] = part;
    __syncthreads();
    if (c < 8) {
        float v = red[c];
        #pragma unroll
        for (int m = 4; m > 0; m >>= 1) v += __shfl_xor_sync(0xffu, v, m);
        if (c == 0) g_bp[o] = qkv_b[o] + v;
    }
}

// ---------------- tf32 tensor-core GEMM ----------------
// Y[b][o][p] = W[o][:] . X[b][:][p] + bias[o] (+resid).  N=1024.
// grid (N/128, M/128, B), block 256 = 8 warps (4 M x 2 N), warp tile 32x64.
__global__ void __launch_bounds__(256) gemm_tf32(const float* __restrict__ W,
                                                 const float* __restrict__ bias,
                                                 const float* __restrict__ X,
                                                 float* __restrict__ Y,
                                                 const float* __restrict__ resid,
                                                 int M, int K) {
    __shared__ float Ws[128 * 36];   // [o][k] stride 36
    __shared__ float Xs[32 * 136];   // [k][n] stride 136

    int tid = threadIdx.x;
    int w = tid >> 5, lane = tid & 31, r = lane >> 2, ql = lane & 3;
    int wm = w >> 1, wn = w & 1;
    int pbase = blockIdx.x * 128, obase = blockIdx.y * 128, b = blockIdx.z;
    const float* Xb = X + (size_t)b * K * 1024;

    float acc[2][8][4];
    #pragma unroll
    for (int t = 0; t < 2; t++)
        #pragma unroll
        for (int nb = 0; nb < 8; nb++)
            #pragma unroll
            for (int j = 0; j < 4; j++) acc[t][nb][j] = 0.f;

    const int orow = wm * 32, ncol = wn * 64;

    for (int kc = 0; kc < K; kc += 32) {
        __syncthreads();
        #pragma unroll 4
        for (int idx = tid; idx < 128 * 32; idx += 256) {
            int o = idx >> 5, k = idx & 31;
            Ws[o * 36 + k] = ftf32(W[(size_t)(obase + o) * K + kc + k]);
        }
        #pragma unroll 4
        for (int idx = tid; idx < 32 * 128; idx += 256) {
            int k = idx >> 7, n = idx & 127;
            Xs[k * 136 + n] = ftf32(Xb[(size_t)(kc + k) * 1024 + pbase + n]);
        }
        __syncthreads();

        #pragma unroll
        for (int kk = 0; kk < 4; kk++) {
            unsigned a[2][4];
            #pragma unroll
            for (int t = 0; t < 2; t++) {
                int o0 = orow + t * 16 + r;
                a[t][0] = __float_as_uint(Ws[o0 * 36 + kk * 8 + ql]);
                a[t][1] = __float_as_uint(Ws[(o0 + 8) * 36 + kk * 8 + ql]);
                a[t][2] = __float_as_uint(Ws[o0 * 36 + kk * 8 + ql + 4]);
                a[t][3] = __float_as_uint(Ws[(o0 + 8) * 36 + kk * 8 + ql + 4]);
            }
            #pragma unroll
            for (int nb = 0; nb < 8; nb++) {
                unsigned b0 = __float_as_uint(Xs[(kk * 8 + ql) * 136 + ncol + nb * 8 + r]);
                unsigned b1 = __float_as_uint(Xs[(kk * 8 + ql + 4) * 136 + ncol + nb * 8 + r]);
                mma_tf32(acc[0][nb], a[0], b0, b1);
                mma_tf32(acc[1][nb], a[1], b0, b1);
            }
        }
    }

    // epilogue: float2 stores (c pairs contiguous)
    #pragma unroll
    for (int t = 0; t < 2; t++) {
        int o0 = obase + orow + t * 16 + r;
        float bv0 = bias[o0], bv1 = bias[o0 + 8];
        #pragma unroll
        for (int nb = 0; nb < 8; nb++) {
            int col = pbase + ncol + nb * 8 + 2 * ql;
            size_t i0 = ((size_t)b * M + o0) * 1024 + col;
            size_t i1 = ((size_t)b * M + o0 + 8) * 1024 + col;
            float2 v0 = make_float2(acc[t][nb][0] + bv0, acc[t][nb][1] + bv0);
            float2 v1 = make_float2(acc[t][nb][2] + bv1, acc[t][nb][3] + bv1);
            if (resid) {
                float2 r0 = *(const float2*)&resid[i0];
                float2 r1 = *(const float2*)&resid[i1];
                v0.x += r0.x; v0.y += r0.y; v1.x += r1.x; v1.y += r1.y;
            }
            *(float2*)&Y[i0] = v0;
            *(float2*)&Y[i1] = v1;
        }
    }
}

// ---------------- kernel C: fused flash attention (tf32, warp M=32) ----------------
// qkv layout: [b][head*192 + {q:0..63, k:64..127, v:128..191}][p]
// grid (4 qtiles, 4 heads, 16 batch), block 256 (8 warps), warp owns 32 q-rows.
#define FL_KS (64 * 68)
#define FL_VS (64 * 72)
#define FL_PS (256 * 76)
#define FL_SMEM_FLOATS (FL_KS + FL_VS + FL_PS)

__global__ void __launch_bounds__(256) flash_k(const float* __restrict__ qkv,
                                               float* __restrict__ av) {
    extern __shared__ float sm[];
    float* Ks = sm;                 // [key][c] stride 68
    float* Vs = Ks + FL_KS;         // [key][c] stride 72
    float* Ps = Vs + FL_VS;         // [q][k]   stride 76 (also Q stage / out stage)

    int tid = threadIdx.x;
    int w = tid >> 5, lane = tid & 31, r = lane >> 2, ql = lane & 3;
    int qb = blockIdx.x * 256;
    int h  = blockIdx.y;
    int b  = blockIdx.z;

    const size_t hb = ((size_t)b * 768 + (size_t)h * 192) * 1024;
    const float* Qg = qkv + hb;
    const float* Kg = qkv + hb + 64 * 1024;
    const float* Vg = qkv + hb + 128 * 1024;
    const float QSC = 0.0625f * 1.44269504088896340736f;  // 1/sqrt(256) * log2(e)

    // stage Q [q][c] into Ps (scaled, tf32)
    for (int idx = tid; idx < 64 * 256; idx += 256) {
        int c = idx >> 8, q = idx & 255;
        Ps[q * 76 + c] = ftf32(Qg[(size_t)c * 1024 + qb + q] * QSC);
    }
    __syncthreads();

    // hoist Q fragments to registers (64 regs)
    const int qrow = w * 32;
    unsigned qf[2][8][4];
    #pragma unroll
    for (int t = 0; t < 2; t++)
        #pragma unroll
        for (int kk = 0; kk < 8; kk++) {
            int q0 = qrow + t * 16 + r;
            qf[t][kk][0] = __float_as_uint(Ps[q0 * 76 + kk * 8 + ql]);
            qf[t][kk][1] = __float_as_uint(Ps[(q0 + 8) * 76 + kk * 8 + ql]);
            qf[t][kk][2] = __float_as_uint(Ps[q0 * 76 + kk * 8 + ql + 4]);
            qf[t][kk][3] = __float_as_uint(Ps[(q0 + 8) * 76 + kk * 8 + ql + 4]);
        }

    float m[2][2] = {{-1e30f, -1e30f}, {-1e30f, -1e30f}};
    float l[2][2] = {{0.f, 0.f}, {0.f, 0.f}};
    float O[2][8][4];
    #pragma unroll
    for (int t = 0; t < 2; t++)
        #pragma unroll
        for (int nb = 0; nb < 8; nb++)
            #pragma unroll
            for (int j = 0; j < 4; j++) O[t][nb][j] = 0.f;

    for (int kt = 0; kt < 16; kt++) {
        __syncthreads();
        int kbase = kt * 64;
        #pragma unroll 4
        for (int idx = tid; idx < 64 * 64; idx += 256) {
            int c = idx >> 6, k = idx & 63;
            Ks[k * 68 + c] = ftf32(Kg[(size_t)c * 1024 + kbase + k]);
            Vs[k * 72 + c] = ftf32(Vg[(size_t)c * 1024 + kbase + k]);
        }
        __syncthreads();

        // ---- S = Q K^T : 32 rows x 64 keys per warp ----
        float S[2][8][4];
        #pragma unroll
        for (int t = 0; t < 2; t++)
            #pragma unroll
            for (int nb = 0; nb < 8; nb++)
                #pragma unroll
                for (int j = 0; j < 4; j++) S[t][nb][j] = 0.f;

        #pragma unroll
        for (int kk = 0; kk < 8; kk++) {
            #pragma unroll
            for (int nb = 0; nb < 8; nb++) {
                unsigned b0 = __float_as_uint(Ks[(nb * 8 + r) * 68 + kk * 8 + ql]);
                unsigned b1 = __float_as_uint(Ks[(nb * 8 + r) * 68 + kk * 8 + ql + 4]);
                mma_tf32(S[0][nb], qf[0][kk], b0, b1);
                mma_tf32(S[1][nb], qf[1][kk], b0, b1);
            }
        }

        // ---- online softmax per row-tile ----
        #pragma unroll
        for (int t = 0; t < 2; t++) {
            float mx0 = -1e30f, mx1 = -1e30f;
            #pragma unroll
            for (int nb = 0; nb < 8; nb++) {
                mx0 = fmaxf(mx0, fmaxf(S[t][nb][0], S[t][nb][1]));
                mx1 = fmaxf(mx1, fmaxf(S[t][nb][2], S[t][nb][3]));
            }
            mx0 = fmaxf(mx0, __shfl_xor_sync(0xffffffffu, mx0, 1));
            mx0 = fmaxf(mx0, __shfl_xor_sync(0xffffffffu, mx0, 2));
            mx1 = fmaxf(mx1, __shfl_xor_sync(0xffffffffu, mx1, 1));
            mx1 = fmaxf(mx1, __shfl_xor_sync(0xffffffffu, mx1, 2));

            float mn0 = fmaxf(m[t][0], mx0), mn1 = fmaxf(m[t][1], mx1);
            float al0 = fexp2(m[t][0] - mn0), al1 = fexp2(m[t][1] - mn1);
            m[t][0] = mn0; m[t][1] = mn1;

            int q0 = qrow + t * 16 + r;
            float rs0 = 0.f, rs1 = 0.f;
            #pragma unroll
            for (int nb = 0; nb < 8; nb++) {
                float p0 = fexp2(S[t][nb][0] - mn0);
                float p1 = fexp2(S[t][nb][1] - mn0);
                float p2 = fexp2(S[t][nb][2] - mn1);
                float p3 = fexp2(S[t][nb][3] - mn1);
                rs0 += p0 + p1; rs1 += p2 + p3;
                Ps[q0 * 76 + nb * 8 + 2 * ql]           = __uint_as_float(f2tf32(p0));
                Ps[q0 * 76 + nb * 8 + 2 * ql + 1]       = __uint_as_float(f2tf32(p1));
                Ps[(q0 + 8) * 76 + nb * 8 + 2 * ql]     = __uint_as_float(f2tf32(p2));
                Ps[(q0 + 8) * 76 + nb * 8 + 2 * ql + 1] = __uint_as_float(f2tf32(p3));
            }
            rs0 += __shfl_xor_sync(0xffffffffu, rs0, 1);
            rs0 += __shfl_xor_sync(0xffffffffu, rs0, 2);
            rs1 += __shfl_xor_sync(0xffffffffu, rs1, 1);
            rs1 += __shfl_xor_sync(0xffffffffu, rs1, 2);
            l[t][0] = l[t][0] * al0 + rs0;
            l[t][1] = l[t][1] * al1 + rs1;

            #pragma unroll
            for (int nb = 0; nb < 8; nb++) {
                O[t][nb][0] *= al0; O[t][nb][1] *= al0;
                O[t][nb][2] *= al1; O[t][nb][3] *= al1;
            }
        }
        __syncwarp();

        // ---- O += P V ----
        #pragma unroll
        for (int kk = 0; kk < 8; kk++) {
            unsigned a[2][4];
            #pragma unroll
            for (int t = 0; t < 2; t++) {
                int q0 = qrow + t * 16 + r;
                a[t][0] = __float_as_uint(Ps[q0 * 76 + kk * 8 + ql]);
                a[t][1] = __float_as_uint(Ps[(q0 + 8) * 76 + kk * 8 + ql]);
                a[t][2] = __float_as_uint(Ps[q0 * 76 + kk * 8 + ql + 4]);
                a[t][3] = __float_as_uint(Ps[(q0 + 8) * 76 + kk * 8 + ql + 4]);
            }
            #pragma unroll
            for (int nb = 0; nb < 8; nb++) {
                unsigned b0 = __float_as_uint(Vs[(kk * 8 + ql) * 72 + nb * 8 + r]);
                unsigned b1 = __float_as_uint(Vs[(kk * 8 + ql + 4) * 72 + nb * 8 + r]);
                mma_tf32(O[0][nb], a[0], b0, b1);
                mma_tf32(O[1][nb], a[1], b0, b1);
            }
        }
    }
    __syncthreads();

    // ---- finalize: O /= l, stage [c][q] (stride 260) for coalesced store ----
    #pragma unroll
    for (int t = 0; t < 2; t++) {
        float inv0 = 1.f / l[t][0], inv1 = 1.f / l[t][1];
        int q0 = qrow + t * 16 + r;
        #pragma unroll
        for (int nb = 0; nb < 8; nb++) {
            int c = nb * 8 + 2 * ql;
            Ps[c * 260 + q0]           = O[t][nb][0] * inv0;
            Ps[(c + 1) * 260 + q0]     = O[t][nb][1] * inv0;
            Ps[c * 260 + q0 + 8]       = O[t][nb][2] * inv1;
            Ps[(c + 1) * 260 + q0 + 8] = O[t][nb][3] * inv1;
        }
    }
    __syncthreads();

    size_t ob = ((size_t)b * 256 + (size_t)h * 64) * 1024 + qb;
    for (int idx = tid; idx < 64 * 256; idx += 256) {
        int c = idx >> 8, q = idx & 255;
        av[ob + (size_t)c * 1024 + q] = Ps[c * 260 + q];
    }
}

// ---------------- launcher ----------------
extern "C" void kernel_launch(void* const* d_in, const int* in_sizes, int n_in,
                              void* d_out, int out_size) {
    const float* x      = (const float*)d_in[0];
    const float* gamma  = (const float*)d_in[1];
    const float* beta   = (const float*)d_in[2];
    const float* rmean  = (const float*)d_in[3];
    const float* rvar   = (const float*)d_in[4];
    const float* qkv_w  = (const float*)d_in[5];
    const float* qkv_b  = (const float*)d_in[6];
    const float* out_w  = (const float*)d_in[7];
    const float* out_b  = (const float*)d_in[8];

    float *Wp, *bp, *qkvbuf, *avbuf;
    cudaGetSymbolAddress((void**)&Wp,     g_Wp);
    cudaGetSymbolAddress((void**)&bp,     g_bp);
    cudaGetSymbolAddress((void**)&qkvbuf, g_qkv);
    cudaGetSymbolAddress((void**)&avbuf,  g_av);

    // A: fold BN into QKV weights
    fold_k<<<768, 256>>>(qkv_w, qkv_b, gamma, beta, rmean, rvar);

    // B: QKV = W' x + b'   (tf32 tensor cores)
    gemm_tf32<<<dim3(8, 6, 16), 256>>>(Wp, bp, x, qkvbuf, nullptr, 768, 256);

    // C: fused attention (tf32 tensor cores, warp M=32)
    size_t smem = FL_SMEM_FLOATS * sizeof(float);
    cudaFuncSetAttribute(flash_k, cudaFuncAttributeMaxDynamicSharedMemorySize, (int)smem);
    flash_k<<<dim3(4, 4, 16), 256, smem>>>(qkvbuf, avbuf);

    // D: out = x + out_w @ av + out_b   (tf32 tensor cores)
    gemm_tf32<<<dim3(8, 2, 16), 256>>>(out_w, out_b, avbuf, (float*)d_out, x, 256, 256);
}

// round 4
// speedup vs baseline: 4.2335x; 1.7768x over previous
#include <cuda_runtime.h>
#include <cstdint>

#define EPSV 1e-5f

// ---------------- scratch ----------------
__device__ float g_Wp[768 * 256];
__device__ float g_bp[768];
__device__ float g_qkv[16 * 768 * 1024];   // [b][o][p]
__device__ float g_av[16 * 256 * 1024];    // [b][c][p]

// ---------------- helpers ----------------
__device__ __forceinline__ float fexp2(float x) {
    float r; asm("ex2.approx.ftz.f32 %0, %1;" : "=f"(r) : "f"(x)); return r;
}
__device__ __forceinline__ void mma_tf32(float c[4], const unsigned a[4],
                                         unsigned b0, unsigned b1) {
    asm volatile("mma.sync.aligned.m16n8k8.row.col.f32.tf32.tf32.f32 "
                 "{%0,%1,%2,%3}, {%4,%5,%6,%7}, {%8,%9}, {%0,%1,%2,%3};"
                 : "+f"(c[0]), "+f"(c[1]), "+f"(c[2]), "+f"(c[3])
                 : "r"(a[0]), "r"(a[1]), "r"(a[2]), "r"(a[3]), "r"(b0), "r"(b1));
}
__device__ __forceinline__ void cp16(uint32_t dst, const float* src) {
    asm volatile("cp.async.cg.shared.global [%0], [%1], 16;" :: "r"(dst), "l"(src));
}
__device__ __forceinline__ void cp_commit() { asm volatile("cp.async.commit_group;"); }
template<int N> __device__ __forceinline__ void cp_wait() {
    asm volatile("cp.async.wait_group %0;" :: "n"(N));
}

// ---------------- kernel A: fold BN into QKV weights ----------------
__global__ void fold_k(const float* __restrict__ qkv_w, const float* __restrict__ qkv_b,
                       const float* __restrict__ gamma, const float* __restrict__ beta,
                       const float* __restrict__ mean,  const float* __restrict__ var) {
    int o = blockIdx.x;
    int c = threadIdx.x;
    float sc = gamma[c] * rsqrtf(var[c] + EPSV);
    float sh = beta[c] - mean[c] * sc;
    float w = qkv_w[o * 256 + c];
    g_Wp[o * 256 + c] = w * sc;
    float part = w * sh;
    __shared__ float red[8];
    #pragma unroll
    for (int m = 16; m > 0; m >>= 1) part += __shfl_xor_sync(0xffffffffu, part, m);
    if ((c & 31) == 0) red[c >> 5] = part;
    __syncthreads();
    if (c < 8) {
        float v = red[c];
        #pragma unroll
        for (int m = 4; m > 0; m >>= 1) v += __shfl_xor_sync(0xffu, v, m);
        if (c == 0) g_bp[o] = qkv_b[o] + v;
    }
}

// ---------------- tf32 GEMM with cp.async double buffering ----------------
// Y[b][o][p] = W[o][:] . X[b][:][p] + bias[o] (+resid).  N=1024, K=256.
// buffers: Ws [o][k] 128x36, Xs [k][n] 32x136 (x2 each, dynamic smem)
#define GW (128 * 36)
#define GX (32 * 136)
#define GEMM_SMEM_FLOATS (2 * (GW + GX))

__device__ __forceinline__ void gemm_load(uint32_t wsb, uint32_t xsb,
                                          const float* W, const float* Xb,
                                          int obase, int pbase, int kc, int K, int tid) {
    #pragma unroll
    for (int idx = tid; idx < 2048; idx += 256) {
        if (idx < 1024) {
            int o = idx >> 3, f4 = idx & 7;
            cp16(wsb + (uint32_t)(o * 36 + f4 * 4) * 4,
                 W + (size_t)(obase + o) * K + kc + f4 * 4);
        } else {
            int j = idx - 1024;
            int k = j >> 5, f4 = j & 31;
            cp16(xsb + (uint32_t)(k * 136 + f4 * 4) * 4,
                 Xb + (size_t)(kc + k) * 1024 + pbase + f4 * 4);
        }
    }
}

__global__ void __launch_bounds__(256, 2) gemm_tf32(const float* __restrict__ W,
                                                    const float* __restrict__ bias,
                                                    const float* __restrict__ X,
                                                    float* __restrict__ Y,
                                                    const float* __restrict__ resid,
                                                    int M, int K) {
    extern __shared__ float sg[];
    float* Ws[2] = { sg, sg + GW };
    float* Xs[2] = { sg + 2 * GW, sg + 2 * GW + GX };
    uint32_t wsb[2], xsb[2];
    wsb[0] = (uint32_t)__cvta_generic_to_shared(Ws[0]);
    wsb[1] = (uint32_t)__cvta_generic_to_shared(Ws[1]);
    xsb[0] = (uint32_t)__cvta_generic_to_shared(Xs[0]);
    xsb[1] = (uint32_t)__cvta_generic_to_shared(Xs[1]);

    int tid = threadIdx.x;
    int w = tid >> 5, lane = tid & 31, r = lane >> 2, ql = lane & 3;
    int wm = w >> 1, wn = w & 1;
    int pbase = blockIdx.x * 128, obase = blockIdx.y * 128, b = blockIdx.z;
    const float* Xb = X + (size_t)b * K * 1024;

    float acc[2][8][4];
    #pragma unroll
    for (int t = 0; t < 2; t++)
        #pragma unroll
        for (int nb = 0; nb < 8; nb++)
            #pragma unroll
            for (int j = 0; j < 4; j++) acc[t][nb][j] = 0.f;

    const int orow = wm * 32, ncol = wn * 64;
    const int NIT = K / 32;   // 8

    gemm_load(wsb[0], xsb[0], W, Xb, obase, pbase, 0, K, tid);
    cp_commit();

    for (int it = 0; it < NIT; it++) {
        if (it < NIT - 1) {
            gemm_load(wsb[(it + 1) & 1], xsb[(it + 1) & 1], W, Xb,
                      obase, pbase, (it + 1) * 32, K, tid);
            cp_commit();
            cp_wait<1>();
        } else {
            cp_wait<0>();
        }
        __syncthreads();

        float* Wc = Ws[it & 1];
        float* Xc = Xs[it & 1];
        #pragma unroll
        for (int kk = 0; kk < 4; kk++) {
            unsigned a[2][4];
            #pragma unroll
            for (int t = 0; t < 2; t++) {
                int o0 = orow + t * 16 + r;
                a[t][0] = __float_as_uint(Wc[o0 * 36 + kk * 8 + ql]);
                a[t][1] = __float_as_uint(Wc[(o0 + 8) * 36 + kk * 8 + ql]);
                a[t][2] = __float_as_uint(Wc[o0 * 36 + kk * 8 + ql + 4]);
                a[t][3] = __float_as_uint(Wc[(o0 + 8) * 36 + kk * 8 + ql + 4]);
            }
            #pragma unroll
            for (int nb = 0; nb < 8; nb++) {
                unsigned b0 = __float_as_uint(Xc[(kk * 8 + ql) * 136 + ncol + nb * 8 + r]);
                unsigned b1 = __float_as_uint(Xc[(kk * 8 + ql + 4) * 136 + ncol + nb * 8 + r]);
                mma_tf32(acc[0][nb], a[0], b0, b1);
                mma_tf32(acc[1][nb], a[1], b0, b1);
            }
        }
        __syncthreads();
    }

    #pragma unroll
    for (int t = 0; t < 2; t++) {
        int o0 = obase + orow + t * 16 + r;
        float bv0 = bias[o0], bv1 = bias[o0 + 8];
        #pragma unroll
        for (int nb = 0; nb < 8; nb++) {
            int col = pbase + ncol + nb * 8 + 2 * ql;
            size_t i0 = ((size_t)b * M + o0) * 1024 + col;
            size_t i1 = ((size_t)b * M + o0 + 8) * 1024 + col;
            float2 v0 = make_float2(acc[t][nb][0] + bv0, acc[t][nb][1] + bv0);
            float2 v1 = make_float2(acc[t][nb][2] + bv1, acc[t][nb][3] + bv1);
            if (resid) {
                float2 r0 = *(const float2*)&resid[i0];
                float2 r1 = *(const float2*)&resid[i1];
                v0.x += r0.x; v0.y += r0.y; v1.x += r1.x; v1.y += r1.y;
            }
            *(float2*)&Y[i0] = v0;
            *(float2*)&Y[i1] = v1;
        }
    }
}

// ---------------- flash attention: tf32 + cp.async double buffering ----------------
// grid (4 qtiles, 4 heads, 16 batch), block 256 (8 warps), warp owns 32 q-rows.
// smem: union U (19456 fl: Q stage 64x264 / P 256x76 / out 64x260),
//       K bufs 2x(64x72), V bufs 2x(64x68)
#define FL_U  19456
#define FL_KSTR 72
#define FL_VSTR 68
#define FL_KSZ (64 * FL_KSTR)
#define FL_VSZ (64 * FL_VSTR)
#define FL_SMEM_FLOATS (FL_U + 2 * FL_KSZ + 2 * FL_VSZ)

__global__ void __launch_bounds__(256) flash_k(const float* __restrict__ qkv,
                                               float* __restrict__ av) {
    extern __shared__ float sm[];
    float* Ps = sm;                                // union region
    float* Ksb[2] = { sm + FL_U, sm + FL_U + FL_KSZ };
    float* Vsb[2] = { sm + FL_U + 2 * FL_KSZ, sm + FL_U + 2 * FL_KSZ + FL_VSZ };
    uint32_t psb = (uint32_t)__cvta_generic_to_shared(Ps);
    uint32_t ksb[2], vsb[2];
    ksb[0] = (uint32_t)__cvta_generic_to_shared(Ksb[0]);
    ksb[1] = (uint32_t)__cvta_generic_to_shared(Ksb[1]);
    vsb[0] = (uint32_t)__cvta_generic_to_shared(Vsb[0]);
    vsb[1] = (uint32_t)__cvta_generic_to_shared(Vsb[1]);

    int tid = threadIdx.x;
    int w = tid >> 5, lane = tid & 31, r = lane >> 2, ql = lane & 3;
    int qb = blockIdx.x * 256;
    int h  = blockIdx.y;
    int b  = blockIdx.z;

    const size_t hb = ((size_t)b * 768 + (size_t)h * 192) * 1024;
    const float* Qg = qkv + hb;
    const float* Kg = qkv + hb + 64 * 1024;
    const float* Vg = qkv + hb + 128 * 1024;
    const float QSC = 0.0625f * 1.44269504088896340736f;  // 1/sqrt(256) * log2(e)

    // group 0: Q stage [c][q] stride 264 into union region
    #pragma unroll
    for (int idx = tid; idx < 4096; idx += 256) {
        int c = idx >> 6, f4 = idx & 63;
        cp16(psb + (uint32_t)(c * 264 + f4 * 4) * 4, Qg + (size_t)c * 1024 + qb + f4 * 4);
    }
    cp_commit();
    // group 1: K/V tile 0
    #pragma unroll
    for (int idx = tid; idx < 2048; idx += 256) {
        if (idx < 1024) {
            int c = idx >> 4, f4 = idx & 15;
            cp16(ksb[0] + (uint32_t)(c * FL_KSTR + f4 * 4) * 4, Kg + (size_t)c * 1024 + f4 * 4);
        } else {
            int j = idx - 1024;
            int c = j >> 4, f4 = j & 15;
            cp16(vsb[0] + (uint32_t)(c * FL_VSTR + f4 * 4) * 4, Vg + (size_t)c * 1024 + f4 * 4);
        }
    }
    cp_commit();
    cp_wait<1>();      // Q ready
    __syncthreads();

    // hoist Q fragments (raw fp32 bits -> tf32 truncation in mma)
    const int qrow = w * 32;
    unsigned qf[2][8][4];
    #pragma unroll
    for (int t = 0; t < 2; t++)
        #pragma unroll
        for (int kk = 0; kk < 8; kk++) {
            int q0 = qrow + t * 16 + r;
            qf[t][kk][0] = __float_as_uint(Ps[(kk * 8 + ql) * 264 + q0]);
            qf[t][kk][1] = __float_as_uint(Ps[(kk * 8 + ql) * 264 + q0 + 8]);
            qf[t][kk][2] = __float_as_uint(Ps[(kk * 8 + ql + 4) * 264 + q0]);
            qf[t][kk][3] = __float_as_uint(Ps[(kk * 8 + ql + 4) * 264 + q0 + 8]);
        }

    float m[2][2] = {{-1e30f, -1e30f}, {-1e30f, -1e30f}};
    float l[2][2] = {{0.f, 0.f}, {0.f, 0.f}};
    float O[2][8][4];
    #pragma unroll
    for (int t = 0; t < 2; t++)
        #pragma unroll
        for (int nb = 0; nb < 8; nb++)
            #pragma unroll
            for (int j = 0; j < 4; j++) O[t][nb][j] = 0.f;

    for (int kt = 0; kt < 16; kt++) {
        if (kt < 15) {
            int nb2 = (kt + 1) & 1;
            int kbase = (kt + 1) * 64;
            #pragma unroll
            for (int idx = tid; idx < 2048; idx += 256) {
                if (idx < 1024) {
                    int c = idx >> 4, f4 = idx & 15;
                    cp16(ksb[nb2] + (uint32_t)(c * FL_KSTR + f4 * 4) * 4,
                         Kg + (size_t)c * 1024 + kbase + f4 * 4);
                } else {
                    int j = idx - 1024;
                    int c = j >> 4, f4 = j & 15;
                    cp16(vsb[nb2] + (uint32_t)(c * FL_VSTR + f4 * 4) * 4,
                         Vg + (size_t)c * 1024 + kbase + f4 * 4);
                }
            }
            cp_commit();
            cp_wait<1>();
        } else {
            cp_wait<0>();
        }
        __syncthreads();

        const float* Kc = Ksb[kt & 1];   // [c][key] stride 72
        const float* Vc = Vsb[kt & 1];   // [c][key] stride 68

        // ---- S = Q K^T ----
        float S[2][8][4];
        #pragma unroll
        for (int t = 0; t < 2; t++)
            #pragma unroll
            for (int nb = 0; nb < 8; nb++)
                #pragma unroll
                for (int j = 0; j < 4; j++) S[t][nb][j] = 0.f;

        #pragma unroll
        for (int kk = 0; kk < 8; kk++) {
            #pragma unroll
            for (int nb = 0; nb < 8; nb++) {
                unsigned b0 = __float_as_uint(Kc[(kk * 8 + ql) * FL_KSTR + nb * 8 + r]);
                unsigned b1 = __float_as_uint(Kc[(kk * 8 + ql + 4) * FL_KSTR + nb * 8 + r]);
                mma_tf32(S[0][nb], qf[0][kk], b0, b1);
                mma_tf32(S[1][nb], qf[1][kk], b0, b1);
            }
        }

        // ---- scale + online softmax ----
        #pragma unroll
        for (int t = 0; t < 2; t++) {
            #pragma unroll
            for (int nb = 0; nb < 8; nb++) {
                S[t][nb][0] *= QSC; S[t][nb][1] *= QSC;
                S[t][nb][2] *= QSC; S[t][nb][3] *= QSC;
            }
            float mx0 = -1e30f, mx1 = -1e30f;
            #pragma unroll
            for (int nb = 0; nb < 8; nb++) {
                mx0 = fmaxf(mx0, fmaxf(S[t][nb][0], S[t][nb][1]));
                mx1 = fmaxf(mx1, fmaxf(S[t][nb][2], S[t][nb][3]));
            }
            mx0 = fmaxf(mx0, __shfl_xor_sync(0xffffffffu, mx0, 1));
            mx0 = fmaxf(mx0, __shfl_xor_sync(0xffffffffu, mx0, 2));
            mx1 = fmaxf(mx1, __shfl_xor_sync(0xffffffffu, mx1, 1));
            mx1 = fmaxf(mx1, __shfl_xor_sync(0xffffffffu, mx1, 2));

            float mn0 = fmaxf(m[t][0], mx0), mn1 = fmaxf(m[t][1], mx1);
            float al0 = fexp2(m[t][0] - mn0), al1 = fexp2(m[t][1] - mn1);
            m[t][0] = mn0; m[t][1] = mn1;

            int q0 = qrow + t * 16 + r;
            float rs0 = 0.f, rs1 = 0.f;
            #pragma unroll
            for (int nb = 0; nb < 8; nb++) {
                float p0 = fexp2(S[t][nb][0] - mn0);
                float p1 = fexp2(S[t][nb][1] - mn0);
                float p2 = fexp2(S[t][nb][2] - mn1);
                float p3 = fexp2(S[t][nb][3] - mn1);
                rs0 += p0 + p1; rs1 += p2 + p3;
                Ps[q0 * 76 + nb * 8 + 2 * ql]           = p0;
                Ps[q0 * 76 + nb * 8 + 2 * ql + 1]       = p1;
                Ps[(q0 + 8) * 76 + nb * 8 + 2 * ql]     = p2;
                Ps[(q0 + 8) * 76 + nb * 8 + 2 * ql + 1] = p3;
            }
            rs0 += __shfl_xor_sync(0xffffffffu, rs0, 1);
            rs0 += __shfl_xor_sync(0xffffffffu, rs0, 2);
            rs1 += __shfl_xor_sync(0xffffffffu, rs1, 1);
            rs1 += __shfl_xor_sync(0xffffffffu, rs1, 2);
            l[t][0] = l[t][0] * al0 + rs0;
            l[t][1] = l[t][1] * al1 + rs1;

            #pragma unroll
            for (int nb = 0; nb < 8; nb++) {
                O[t][nb][0] *= al0; O[t][nb][1] *= al0;
                O[t][nb][2] *= al1; O[t][nb][3] *= al1;
            }
        }
        __syncwarp();

        // ---- O += P V ----
        #pragma unroll
        for (int kk = 0; kk < 8; kk++) {
            unsigned a[2][4];
            #pragma unroll
            for (int t = 0; t < 2; t++) {
                int q0 = qrow + t * 16 + r;
                a[t][0] = __float_as_uint(Ps[q0 * 76 + kk * 8 + ql]);
                a[t][1] = __float_as_uint(Ps[(q0 + 8) * 76 + kk * 8 + ql]);
                a[t][2] = __float_as_uint(Ps[q0 * 76 + kk * 8 + ql + 4]);
                a[t][3] = __float_as_uint(Ps[(q0 + 8) * 76 + kk * 8 + ql + 4]);
            }
            #pragma unroll
            for (int nb = 0; nb < 8; nb++) {
                unsigned b0 = __float_as_uint(Vc[(nb * 8 + r) * FL_VSTR + kk * 8 + ql]);
                unsigned b1 = __float_as_uint(Vc[(nb * 8 + r) * FL_VSTR + kk * 8 + ql + 4]);
                mma_tf32(O[0][nb], a[0], b0, b1);
                mma_tf32(O[1][nb], a[1], b0, b1);
            }
        }
        __syncthreads();
    }

    // ---- finalize: O /= l, stage [c][q] stride 260, coalesced store ----
    #pragma unroll
    for (int t = 0; t < 2; t++) {
        float inv0 = 1.f / l[t][0], inv1 = 1.f / l[t][1];
        int q0 = qrow + t * 16 + r;
        #pragma unroll
        for (int nb = 0; nb < 8; nb++) {
            int c = nb * 8 + 2 * ql;
            Ps[c * 260 + q0]           = O[t][nb][0] * inv0;
            Ps[(c + 1) * 260 + q0]     = O[t][nb][1] * inv0;
            Ps[c * 260 + q0 + 8]       = O[t][nb][2] * inv1;
            Ps[(c + 1) * 260 + q0 + 8] = O[t][nb][3] * inv1;
        }
    }
    __syncthreads();

    size_t ob = ((size_t)b * 256 + (size_t)h * 64) * 1024 + qb;
    for (int idx = tid; idx < 64 * 256; idx += 256) {
        int c = idx >> 8, q = idx & 255;
        av[ob + (size_t)c * 1024 + q] = Ps[c * 260 + q];
    }
}

// ---------------- launcher ----------------
extern "C" void kernel_launch(void* const* d_in, const int* in_sizes, int n_in,
                              void* d_out, int out_size) {
    const float* x      = (const float*)d_in[0];
    const float* gamma  = (const float*)d_in[1];
    const float* beta   = (const float*)d_in[2];
    const float* rmean  = (const float*)d_in[3];
    const float* rvar   = (const float*)d_in[4];
    const float* qkv_w  = (const float*)d_in[5];
    const float* qkv_b  = (const float*)d_in[6];
    const float* out_w  = (const float*)d_in[7];
    const float* out_b  = (const float*)d_in[8];

    float *Wp, *bp, *qkvbuf, *avbuf;
    cudaGetSymbolAddress((void**)&Wp,     g_Wp);
    cudaGetSymbolAddress((void**)&bp,     g_bp);
    cudaGetSymbolAddress((void**)&qkvbuf, g_qkv);
    cudaGetSymbolAddress((void**)&avbuf,  g_av);

    size_t gsmem = GEMM_SMEM_FLOATS * sizeof(float);
    size_t fsmem = FL_SMEM_FLOATS * sizeof(float);
    cudaFuncSetAttribute(gemm_tf32, cudaFuncAttributeMaxDynamicSharedMemorySize, (int)gsmem);
    cudaFuncSetAttribute(flash_k,  cudaFuncAttributeMaxDynamicSharedMemorySize, (int)fsmem);

    fold_k<<<768, 256>>>(qkv_w, qkv_b, gamma, beta, rmean, rvar);
    gemm_tf32<<<dim3(8, 6, 16), 256, gsmem>>>(Wp, bp, x, qkvbuf, nullptr, 768, 256);
    flash_k<<<dim3(4, 4, 16), 256, fsmem>>>(qkvbuf, avbuf);
    gemm_tf32<<<dim3(8, 2, 16), 256, gsmem>>>(out_w, out_b, avbuf, (float*)d_out, x, 256, 256);
}

// round 5
// speedup vs baseline: 6.4655x; 1.5272x over previous
#include <cuda_runtime.h>
#include <cuda_fp16.h>
#include <cstdint>

#define EPSV 1e-5f

// ---------------- scratch ----------------
__device__ float  g_Wp[768 * 256];
__device__ float  g_bp[768];
__device__ __half g_Woh[256 * 256];
__device__ __half g_qkvh[16 * 768 * 1024];   // [b][o][p] fp16
__device__ __half g_avh[16 * 256 * 1024];    // [b][c][p] fp16

// ---------------- helpers ----------------
__device__ __forceinline__ float fexp2(float x) {
    float r; asm("ex2.approx.ftz.f32 %0, %1;" : "=f"(r) : "f"(x)); return r;
}
__device__ __forceinline__ void mma_tf32(float c[4], const unsigned a[4],
                                         unsigned b0, unsigned b1) {
    asm volatile("mma.sync.aligned.m16n8k8.row.col.f32.tf32.tf32.f32 "
                 "{%0,%1,%2,%3}, {%4,%5,%6,%7}, {%8,%9}, {%0,%1,%2,%3};"
                 : "+f"(c[0]), "+f"(c[1]), "+f"(c[2]), "+f"(c[3])
                 : "r"(a[0]), "r"(a[1]), "r"(a[2]), "r"(a[3]), "r"(b0), "r"(b1));
}
__device__ __forceinline__ void mma_f16(float c[4], const unsigned a[4],
                                        unsigned b0, unsigned b1) {
    asm volatile("mma.sync.aligned.m16n8k16.row.col.f32.f16.f16.f32 "
                 "{%0,%1,%2,%3}, {%4,%5,%6,%7}, {%8,%9}, {%0,%1,%2,%3};"
                 : "+f"(c[0]), "+f"(c[1]), "+f"(c[2]), "+f"(c[3])
                 : "r"(a[0]), "r"(a[1]), "r"(a[2]), "r"(a[3]), "r"(b0), "r"(b1));
}
__device__ __forceinline__ unsigned packh2(float lo, float hi) {
    unsigned d; asm("cvt.rn.f16x2.f32 %0, %1, %2;" : "=r"(d) : "f"(hi), "f"(lo)); return d;
}
__device__ __forceinline__ void cp16(uint32_t dst, const void* src) {
    asm volatile("cp.async.cg.shared.global [%0], [%1], 16;" :: "r"(dst), "l"(src));
}
__device__ __forceinline__ void cp_commit() { asm volatile("cp.async.commit_group;"); }
template<int N> __device__ __forceinline__ void cp_wait() {
    asm volatile("cp.async.wait_group %0;" :: "n"(N));
}
__device__ __forceinline__ void ldsm_x4t(unsigned& d0, unsigned& d1,
                                         unsigned& d2, unsigned& d3, uint32_t addr) {
    asm volatile("ldmatrix.sync.aligned.m8n8.x4.trans.shared.b16 {%0,%1,%2,%3}, [%4];"
                 : "=r"(d0), "=r"(d1), "=r"(d2), "=r"(d3) : "r"(addr));
}

// ---------------- kernel A: fold BN into QKV weights ----------------
__global__ void fold_k(const float* __restrict__ qkv_w, const float* __restrict__ qkv_b,
                       const float* __restrict__ gamma, const float* __restrict__ beta,
                       const float* __restrict__ mean,  const float* __restrict__ var) {
    int o = blockIdx.x;
    int c = threadIdx.x;
    float sc = gamma[c] * rsqrtf(var[c] + EPSV);
    float sh = beta[c] - mean[c] * sc;
    float w = qkv_w[o * 256 + c];
    g_Wp[o * 256 + c] = w * sc;
    float part = w * sh;
    __shared__ float red[8];
    #pragma unroll
    for (int m = 16; m > 0; m >>= 1) part += __shfl_xor_sync(0xffffffffu, part, m);
    if ((c & 31) == 0) red[c >> 5] = part;
    __syncthreads();
    if (c < 8) {
        float v = red[c];
        #pragma unroll
        for (int m = 4; m > 0; m >>= 1) v += __shfl_xor_sync(0xffu, v, m);
        if (c == 0) g_bp[o] = qkv_b[o] + v;
    }
}

__global__ void convw_k(const float* __restrict__ w) {
    int i = blockIdx.x * 256 + threadIdx.x;
    g_Woh[i] = __float2half(w[i]);
}

// ---------------- gemm_qkv: tf32 compute (fp32 x), fp16 output ----------------
#define GW (128 * 36)
#define GX (32 * 136)
#define GEMM_SMEM_FLOATS (2 * (GW + GX))

__device__ __forceinline__ void gq_load(uint32_t wsb, uint32_t xsb,
                                        const float* W, const float* Xb,
                                        int obase, int pbase, int kc, int tid) {
    #pragma unroll
    for (int idx = tid; idx < 2048; idx += 256) {
        if (idx < 1024) {
            int o = idx >> 3, f4 = idx & 7;
            cp16(wsb + (uint32_t)(o * 36 + f4 * 4) * 4,
                 W + (size_t)(obase + o) * 256 + kc + f4 * 4);
        } else {
            int j = idx - 1024;
            int k = j >> 5, f4 = j & 31;
            cp16(xsb + (uint32_t)(k * 136 + f4 * 4) * 4,
                 Xb + (size_t)(kc + k) * 1024 + pbase + f4 * 4);
        }
    }
}

__global__ void __launch_bounds__(256, 2) gemm_qkv(const float* __restrict__ W,
                                                   const float* __restrict__ bias,
                                                   const float* __restrict__ X,
                                                   __half* __restrict__ Y) {
    extern __shared__ float sg[];
    float* Ws[2] = { sg, sg + GW };
    float* Xs[2] = { sg + 2 * GW, sg + 2 * GW + GX };
    uint32_t wsb[2], xsb[2];
    wsb[0] = (uint32_t)__cvta_generic_to_shared(Ws[0]);
    wsb[1] = (uint32_t)__cvta_generic_to_shared(Ws[1]);
    xsb[0] = (uint32_t)__cvta_generic_to_shared(Xs[0]);
    xsb[1] = (uint32_t)__cvta_generic_to_shared(Xs[1]);

    int tid = threadIdx.x;
    int w = tid >> 5, lane = tid & 31, r = lane >> 2, ql = lane & 3;
    int wm = w >> 1, wn = w & 1;
    int pbase = blockIdx.x * 128, obase = blockIdx.y * 128, b = blockIdx.z;
    const float* Xb = X + (size_t)b * 256 * 1024;

    float acc[2][8][4];
    #pragma unroll
    for (int t = 0; t < 2; t++)
        #pragma unroll
        for (int nb = 0; nb < 8; nb++)
            #pragma unroll
            for (int j = 0; j < 4; j++) acc[t][nb][j] = 0.f;

    const int orow = wm * 32, ncol = wn * 64;

    gq_load(wsb[0], xsb[0], W, Xb, obase, pbase, 0, tid);
    cp_commit();

    for (int it = 0; it < 8; it++) {
        if (it < 7) {
            gq_load(wsb[(it + 1) & 1], xsb[(it + 1) & 1], W, Xb, obase, pbase, (it + 1) * 32, tid);
            cp_commit();
            cp_wait<1>();
        } else {
            cp_wait<0>();
        }
        __syncthreads();

        float* Wc = Ws[it & 1];
        float* Xc = Xs[it & 1];
        #pragma unroll
        for (int kk = 0; kk < 4; kk++) {
            unsigned a[2][4];
            #pragma unroll
            for (int t = 0; t < 2; t++) {
                int o0 = orow + t * 16 + r;
                a[t][0] = __float_as_uint(Wc[o0 * 36 + kk * 8 + ql]);
                a[t][1] = __float_as_uint(Wc[(o0 + 8) * 36 + kk * 8 + ql]);
                a[t][2] = __float_as_uint(Wc[o0 * 36 + kk * 8 + ql + 4]);
                a[t][3] = __float_as_uint(Wc[(o0 + 8) * 36 + kk * 8 + ql + 4]);
            }
            #pragma unroll
            for (int nb = 0; nb < 8; nb++) {
                unsigned b0 = __float_as_uint(Xc[(kk * 8 + ql) * 136 + ncol + nb * 8 + r]);
                unsigned b1 = __float_as_uint(Xc[(kk * 8 + ql + 4) * 136 + ncol + nb * 8 + r]);
                mma_tf32(acc[0][nb], a[0], b0, b1);
                mma_tf32(acc[1][nb], a[1], b0, b1);
            }
        }
        __syncthreads();
    }

    #pragma unroll
    for (int t = 0; t < 2; t++) {
        int o0 = obase + orow + t * 16 + r;
        float bv0 = bias[o0], bv1 = bias[o0 + 8];
        #pragma unroll
        for (int nb = 0; nb < 8; nb++) {
            int col = pbase + ncol + nb * 8 + 2 * ql;
            size_t i0 = ((size_t)b * 768 + o0) * 1024 + col;
            size_t i1 = ((size_t)b * 768 + o0 + 8) * 1024 + col;
            *(unsigned*)&Y[i0] = packh2(acc[t][nb][0] + bv0, acc[t][nb][1] + bv0);
            *(unsigned*)&Y[i1] = packh2(acc[t][nb][2] + bv1, acc[t][nb][3] + bv1);
        }
    }
}

// ---------------- flash attention: fp16 mma, register P ----------------
// grid (4 qtiles, 4 heads, 16 batch), block 256 (8 warps), warp owns 32 q rows.
#define FH_QSTR 264
#define FH_KSTR 72
#define FH_U   (64 * FH_QSTR)
#define FH_KSZ (64 * FH_KSTR)
#define FH_SMEM_BYTES ((FH_U + 4 * FH_KSZ) * 2)

__global__ void __launch_bounds__(256) flash_h(const __half* __restrict__ qkv,
                                               __half* __restrict__ av) {
    extern __shared__ __half sh[];
    __half* Us = sh;
    __half* Vb[2] = { sh + FH_U + 2 * FH_KSZ, sh + FH_U + 3 * FH_KSZ };
    uint32_t usb = (uint32_t)__cvta_generic_to_shared(Us);
    uint32_t ksb[2], vsb[2];
    ksb[0] = (uint32_t)__cvta_generic_to_shared(sh + FH_U);
    ksb[1] = (uint32_t)__cvta_generic_to_shared(sh + FH_U + FH_KSZ);
    vsb[0] = (uint32_t)__cvta_generic_to_shared(Vb[0]);
    vsb[1] = (uint32_t)__cvta_generic_to_shared(Vb[1]);

    int tid = threadIdx.x;
    int w = tid >> 5, lane = tid & 31, r = lane >> 2, ql = lane & 3;
    int qb = blockIdx.x * 256;
    int h  = blockIdx.y;
    int b  = blockIdx.z;

    const size_t hb = ((size_t)b * 768 + (size_t)h * 192) * 1024;
    const __half* Qg = qkv + hb;
    const __half* Kg = qkv + hb + 64 * 1024;
    const __half* Vg = qkv + hb + 128 * 1024;
    const float QSC = 0.0625f * 1.44269504088896340736f;

    // stage Q [c][q] (2048 16B chunks)
    #pragma unroll
    for (int idx = tid; idx < 2048; idx += 256) {
        int c = idx >> 5, f8 = idx & 31;
        cp16(usb + (uint32_t)(c * FH_QSTR + f8 * 8) * 2, Qg + (size_t)c * 1024 + qb + f8 * 8);
    }
    cp_commit();
    // K/V tile 0
    #pragma unroll
    for (int idx = tid; idx < 1024; idx += 256) {
        if (idx < 512) {
            int c = idx >> 3, f8 = idx & 7;
            cp16(ksb[0] + (uint32_t)(c * FH_KSTR + f8 * 8) * 2, Kg + (size_t)c * 1024 + f8 * 8);
        } else {
            int j = idx - 512;
            int c = j >> 3, f8 = j & 7;
            cp16(vsb[0] + (uint32_t)(c * FH_KSTR + f8 * 8) * 2, Vg + (size_t)c * 1024 + f8 * 8);
        }
    }
    cp_commit();
    cp_wait<1>();
    __syncthreads();

    // Q fragments from [c][q] staging (one-time scalar loads)
    const int qrow = w * 32;
    const unsigned short* Uss = (const unsigned short*)Us;
    unsigned qf[2][4][4];
    #pragma unroll
    for (int t = 0; t < 2; t++)
        #pragma unroll
        for (int kk = 0; kk < 4; kk++) {
            int q0 = qrow + t * 16 + r;
            int c0 = kk * 16 + 2 * ql;
            qf[t][kk][0] = (unsigned)Uss[c0 * FH_QSTR + q0]       | ((unsigned)Uss[(c0 + 1) * FH_QSTR + q0] << 16);
            qf[t][kk][1] = (unsigned)Uss[c0 * FH_QSTR + q0 + 8]   | ((unsigned)Uss[(c0 + 1) * FH_QSTR + q0 + 8] << 16);
            qf[t][kk][2] = (unsigned)Uss[(c0 + 8) * FH_QSTR + q0]     | ((unsigned)Uss[(c0 + 9) * FH_QSTR + q0] << 16);
            qf[t][kk][3] = (unsigned)Uss[(c0 + 8) * FH_QSTR + q0 + 8] | ((unsigned)Uss[(c0 + 9) * FH_QSTR + q0 + 8] << 16);
        }

    // per-lane ldmatrix row offset for K tiles
    int g = lane >> 3, jj = lane & 7;
    uint32_t k_rp = (uint32_t)((((g & 1) * 8 + jj) * FH_KSTR + (g >> 1) * 8) * 2);

    float m[2][2] = {{-1e30f, -1e30f}, {-1e30f, -1e30f}};
    float l[2][2] = {{0.f, 0.f}, {0.f, 0.f}};
    float O[2][8][4];
    #pragma unroll
    for (int t = 0; t < 2; t++)
        #pragma unroll
        for (int nb = 0; nb < 8; nb++)
            #pragma unroll
            for (int j = 0; j < 4; j++) O[t][nb][j] = 0.f;

    for (int kt = 0; kt < 16; kt++) {
        if (kt < 15) {
            int nb2 = (kt + 1) & 1;
            int kbase = (kt + 1) * 64;
            #pragma unroll
            for (int idx = tid; idx < 1024; idx += 256) {
                if (idx < 512) {
                    int c = idx >> 3, f8 = idx & 7;
                    cp16(ksb[nb2] + (uint32_t)(c * FH_KSTR + f8 * 8) * 2,
                         Kg + (size_t)c * 1024 + kbase + f8 * 8);
                } else {
                    int j = idx - 512;
                    int c = j >> 3, f8 = j & 7;
                    cp16(vsb[nb2] + (uint32_t)(c * FH_KSTR + f8 * 8) * 2,
                         Vg + (size_t)c * 1024 + kbase + f8 * 8);
                }
            }
            cp_commit();
            cp_wait<1>();
        } else {
            cp_wait<0>();
        }
        __syncthreads();

        uint32_t kcur = ksb[kt & 1];
        const __half* Vc = Vb[kt & 1];

        // ---- S = Q K^T ----
        float S[2][8][4];
        #pragma unroll
        for (int t = 0; t < 2; t++)
            #pragma unroll
            for (int nb = 0; nb < 8; nb++)
                #pragma unroll
                for (int j = 0; j < 4; j++) S[t][nb][j] = 0.f;

        #pragma unroll
        for (int kk = 0; kk < 4; kk++) {
            #pragma unroll
            for (int nb2 = 0; nb2 < 8; nb2 += 2) {
                unsigned d0, d1, d2, d3;
                ldsm_x4t(d0, d1, d2, d3,
                         kcur + (uint32_t)((kk * 16 * FH_KSTR + nb2 * 8) * 2) + k_rp);
                mma_f16(S[0][nb2],     qf[0][kk], d0, d1);
                mma_f16(S[1][nb2],     qf[1][kk], d0, d1);
                mma_f16(S[0][nb2 + 1], qf[0][kk], d2, d3);
                mma_f16(S[1][nb2 + 1], qf[1][kk], d2, d3);
            }
        }

        // ---- scale + online softmax (p overwrites S) ----
        #pragma unroll
        for (int t = 0; t < 2; t++) {
            #pragma unroll
            for (int nb = 0; nb < 8; nb++) {
                S[t][nb][0] *= QSC; S[t][nb][1] *= QSC;
                S[t][nb][2] *= QSC; S[t][nb][3] *= QSC;
            }
            float mx0 = -1e30f, mx1 = -1e30f;
            #pragma unroll
            for (int nb = 0; nb < 8; nb++) {
                mx0 = fmaxf(mx0, fmaxf(S[t][nb][0], S[t][nb][1]));
                mx1 = fmaxf(mx1, fmaxf(S[t][nb][2], S[t][nb][3]));
            }
            mx0 = fmaxf(mx0, __shfl_xor_sync(0xffffffffu, mx0, 1));
            mx0 = fmaxf(mx0, __shfl_xor_sync(0xffffffffu, mx0, 2));
            mx1 = fmaxf(mx1, __shfl_xor_sync(0xffffffffu, mx1, 1));
            mx1 = fmaxf(mx1, __shfl_xor_sync(0xffffffffu, mx1, 2));

            float mn0 = fmaxf(m[t][0], mx0), mn1 = fmaxf(m[t][1], mx1);
            float al0 = fexp2(m[t][0] - mn0), al1 = fexp2(m[t][1] - mn1);
            m[t][0] = mn0; m[t][1] = mn1;

            float rs0 = 0.f, rs1 = 0.f;
            #pragma unroll
            for (int nb = 0; nb < 8; nb++) {
                S[t][nb][0] = fexp2(S[t][nb][0] - mn0);
                S[t][nb][1] = fexp2(S[t][nb][1] - mn0);
                S[t][nb][2] = fexp2(S[t][nb][2] - mn1);
                S[t][nb][3] = fexp2(S[t][nb][3] - mn1);
                rs0 += S[t][nb][0] + S[t][nb][1];
                rs1 += S[t][nb][2] + S[t][nb][3];
            }
            rs0 += __shfl_xor_sync(0xffffffffu, rs0, 1);
            rs0 += __shfl_xor_sync(0xffffffffu, rs0, 2);
            rs1 += __shfl_xor_sync(0xffffffffu, rs1, 1);
            rs1 += __shfl_xor_sync(0xffffffffu, rs1, 2);
            l[t][0] = l[t][0] * al0 + rs0;
            l[t][1] = l[t][1] * al1 + rs1;

            #pragma unroll
            for (int nb = 0; nb < 8; nb++) {
                O[t][nb][0] *= al0; O[t][nb][1] *= al0;
                O[t][nb][2] *= al1; O[t][nb][3] *= al1;
            }
        }

        // ---- pack P to fp16 A-frags in registers ----
        unsigned pa[2][4][4];
        #pragma unroll
        for (int t = 0; t < 2; t++)
            #pragma unroll
            for (int kk = 0; kk < 4; kk++) {
                pa[t][kk][0] = packh2(S[t][2 * kk][0],     S[t][2 * kk][1]);
                pa[t][kk][1] = packh2(S[t][2 * kk][2],     S[t][2 * kk][3]);
                pa[t][kk][2] = packh2(S[t][2 * kk + 1][0], S[t][2 * kk + 1][1]);
                pa[t][kk][3] = packh2(S[t][2 * kk + 1][2], S[t][2 * kk + 1][3]);
            }

        // ---- O += P V ----
        #pragma unroll
        for (int kk = 0; kk < 4; kk++) {
            #pragma unroll
            for (int nb = 0; nb < 8; nb++) {
                unsigned b0 = *(const unsigned*)&Vc[(nb * 8 + r) * FH_KSTR + kk * 16 + 2 * ql];
                unsigned b1 = *(const unsigned*)&Vc[(nb * 8 + r) * FH_KSTR + kk * 16 + 2 * ql + 8];
                mma_f16(O[0][nb], pa[0][kk], b0, b1);
                mma_f16(O[1][nb], pa[1][kk], b0, b1);
            }
        }
        __syncthreads();
    }

    // ---- finalize: stage fp16 [c][q], coalesced store ----
    unsigned short* Uw = (unsigned short*)Us;
    #pragma unroll
    for (int t = 0; t < 2; t++) {
        float inv0 = 1.f / l[t][0], inv1 = 1.f / l[t][1];
        int q0 = qrow + t * 16 + r;
        #pragma unroll
        for (int nb = 0; nb < 8; nb++) {
            int c = nb * 8 + 2 * ql;
            Uw[c * FH_QSTR + q0]           = __half_as_ushort(__float2half(O[t][nb][0] * inv0));
            Uw[(c + 1) * FH_QSTR + q0]     = __half_as_ushort(__float2half(O[t][nb][1] * inv0));
            Uw[c * FH_QSTR + q0 + 8]       = __half_as_ushort(__float2half(O[t][nb][2] * inv1));
            Uw[(c + 1) * FH_QSTR + q0 + 8] = __half_as_ushort(__float2half(O[t][nb][3] * inv1));
        }
    }
    __syncthreads();

    size_t ob = ((size_t)b * 256 + (size_t)h * 64) * 1024 + qb;
    for (int idx = tid; idx < 64 * 128; idx += 256) {
        int c = idx >> 7, wd = idx & 127;
        *(unsigned*)&av[ob + (size_t)c * 1024 + wd * 2] = ((unsigned*)Us)[c * (FH_QSTR / 2) + wd];
    }
}

// ---------------- out-projection GEMM: fp16 mma ----------------
#define GO_WS (128 * 40)
#define GO_XS (32 * 136)
#define GO_SMEM_BYTES (2 * (GO_WS + GO_XS) * 2)

__global__ void __launch_bounds__(256, 2) gemm_out(const __half* __restrict__ W,
                                                   const float* __restrict__ bias,
                                                   const __half* __restrict__ X,
                                                   float* __restrict__ Y,
                                                   const float* __restrict__ resid) {
    extern __shared__ __half sgo[];
    __half* Ws[2] = { sgo, sgo + GO_WS };
    __half* Xs[2] = { sgo + 2 * GO_WS, sgo + 2 * GO_WS + GO_XS };
    uint32_t wsb[2], xsb[2];
    wsb[0] = (uint32_t)__cvta_generic_to_shared(Ws[0]);
    wsb[1] = (uint32_t)__cvta_generic_to_shared(Ws[1]);
    xsb[0] = (uint32_t)__cvta_generic_to_shared(Xs[0]);
    xsb[1] = (uint32_t)__cvta_generic_to_shared(Xs[1]);

    int tid = threadIdx.x;
    int w = tid >> 5, lane = tid & 31, r = lane >> 2, ql = lane & 3;
    int wm = w >> 1, wn = w & 1;
    int pbase = blockIdx.x * 128, obase = blockIdx.y * 128, b = blockIdx.z;
    const __half* Xb = X + (size_t)b * 256 * 1024;

    int g = lane >> 3, jj = lane & 7;
    uint32_t x_rp = (uint32_t)((((g & 1) * 8 + jj) * 136 + (g >> 1) * 8) * 2);

    float acc[2][8][4];
    #pragma unroll
    for (int t = 0; t < 2; t++)
        #pragma unroll
        for (int nb = 0; nb < 8; nb++)
            #pragma unroll
            for (int j = 0; j < 4; j++) acc[t][nb][j] = 0.f;

    const int orow = wm * 32, ncol = wn * 64;

    #pragma unroll
    for (int idx = tid; idx < 1024; idx += 256) {
        if (idx < 512) {
            int o = idx >> 2, f8 = idx & 3;
            cp16(wsb[0] + (uint32_t)(o * 40 + f8 * 8) * 2, W + (size_t)(obase + o) * 256 + f8 * 8);
        } else {
            int j = idx - 512;
            int k = j >> 4, f8 = j & 15;
            cp16(xsb[0] + (uint32_t)(k * 136 + f8 * 8) * 2, Xb + (size_t)k * 1024 + pbase + f8 * 8);
        }
    }
    cp_commit();

    for (int it = 0; it < 8; it++) {
        if (it < 7) {
            int nb2 = (it + 1) & 1;
            int kc = (it + 1) * 32;
            #pragma unroll
            for (int idx = tid; idx < 1024; idx += 256) {
                if (idx < 512) {
                    int o = idx >> 2, f8 = idx & 3;
                    cp16(wsb[nb2] + (uint32_t)(o * 40 + f8 * 8) * 2,
                         W + (size_t)(obase + o) * 256 + kc + f8 * 8);
                } else {
                    int j = idx - 512;
                    int k = j >> 4, f8 = j & 15;
                    cp16(xsb[nb2] + (uint32_t)(k * 136 + f8 * 8) * 2,
                         Xb + (size_t)(kc + k) * 1024 + pbase + f8 * 8);
                }
            }
            cp_commit();
            cp_wait<1>();
        } else {
            cp_wait<0>();
        }
        __syncthreads();

        const __half* Wc = Ws[it & 1];
        uint32_t xcur = xsb[it & 1];
        #pragma unroll
        for (int kk = 0; kk < 2; kk++) {
            unsigned a[2][4];
            #pragma unroll
            for (int t = 0; t < 2; t++) {
                int o0 = orow + t * 16 + r;
                a[t][0] = *(const unsigned*)&Wc[o0 * 40 + kk * 16 + 2 * ql];
                a[t][1] = *(const unsigned*)&Wc[(o0 + 8) * 40 + kk * 16 + 2 * ql];
                a[t][2] = *(const unsigned*)&Wc[o0 * 40 + kk * 16 + 2 * ql + 8];
                a[t][3] = *(const unsigned*)&Wc[(o0 + 8) * 40 + kk * 16 + 2 * ql + 8];
            }
            #pragma unroll
            for (int nb2 = 0; nb2 < 8; nb2 += 2) {
                unsigned d0, d1, d2, d3;
                ldsm_x4t(d0, d1, d2, d3,
                         xcur + (uint32_t)((kk * 16 * 136 + ncol + nb2 * 8) * 2) + x_rp);
                mma_f16(acc[0][nb2],     a[0], d0, d1);
                mma_f16(acc[1][nb2],     a[1], d0, d1);
                mma_f16(acc[0][nb2 + 1], a[0], d2, d3);
                mma_f16(acc[1][nb2 + 1], a[1], d2, d3);
            }
        }
        __syncthreads();
    }

    #pragma unroll
    for (int t = 0; t < 2; t++) {
        int o0 = obase + orow + t * 16 + r;
        float bv0 = bias[o0], bv1 = bias[o0 + 8];
        #pragma unroll
        for (int nb = 0; nb < 8; nb++) {
            int col = pbase + ncol + nb * 8 + 2 * ql;
            size_t i0 = ((size_t)b * 256 + o0) * 1024 + col;
            size_t i1 = ((size_t)b * 256 + o0 + 8) * 1024 + col;
            float2 r0 = *(const float2*)&resid[i0];
            float2 r1 = *(const float2*)&resid[i1];
            float2 v0 = make_float2(acc[t][nb][0] + bv0 + r0.x, acc[t][nb][1] + bv0 + r0.y);
            float2 v1 = make_float2(acc[t][nb][2] + bv1 + r1.x, acc[t][nb][3] + bv1 + r1.y);
            *(float2*)&Y[i0] = v0;
            *(float2*)&Y[i1] = v1;
        }
    }
}

// ---------------- launcher ----------------
extern "C" void kernel_launch(void* const* d_in, const int* in_sizes, int n_in,
                              void* d_out, int out_size) {
    const float* x      = (const float*)d_in[0];
    const float* gamma  = (const float*)d_in[1];
    const float* beta   = (const float*)d_in[2];
    const float* rmean  = (const float*)d_in[3];
    const float* rvar   = (const float*)d_in[4];
    const float* qkv_w  = (const float*)d_in[5];
    const float* qkv_b  = (const float*)d_in[6];
    const float* out_w  = (const float*)d_in[7];
    const float* out_b  = (const float*)d_in[8];

    float *Wp, *bp;
    __half *Woh, *qkvh, *avh;
    cudaGetSymbolAddress((void**)&Wp,   g_Wp);
    cudaGetSymbolAddress((void**)&bp,   g_bp);
    cudaGetSymbolAddress((void**)&Woh,  g_Woh);
    cudaGetSymbolAddress((void**)&qkvh, g_qkvh);
    cudaGetSymbolAddress((void**)&avh,  g_avh);

    size_t gsmem = GEMM_SMEM_FLOATS * sizeof(float);
    cudaFuncSetAttribute(gemm_qkv, cudaFuncAttributeMaxDynamicSharedMemorySize, (int)gsmem);
    cudaFuncSetAttribute(flash_h,  cudaFuncAttributeMaxDynamicSharedMemorySize, FH_SMEM_BYTES);
    cudaFuncSetAttribute(gemm_out, cudaFuncAttributeMaxDynamicSharedMemorySize, GO_SMEM_BYTES);

    fold_k<<<768, 256>>>(qkv_w, qkv_b, gamma, beta, rmean, rvar);
    convw_k<<<256, 256>>>(out_w);
    gemm_qkv<<<dim3(8, 6, 16), 256, gsmem>>>(Wp, bp, x, qkvh);
    flash_h<<<dim3(4, 4, 16), 256, FH_SMEM_BYTES>>>(qkvh, avh);
    gemm_out<<<dim3(8, 2, 16), 256, GO_SMEM_BYTES>>>(Woh, out_b, avh, (float*)d_out, x);
}

// round 6
// speedup vs baseline: 7.4221x; 1.1480x over previous
#include <cuda_runtime.h>
#include <cuda_fp16.h>
#include <cstdint>

#define EPSV 1e-5f
#define QSCALE (0.0625f * 1.44269504088896340736f)   // 1/sqrt(256) * log2(e)

// ---------------- scratch ----------------
__device__ __half g_Wh[768 * 256];           // BN+scale folded QKV weight (fp16)
__device__ float  g_bp[768];                 // folded QKV bias (fp32, Q rows scaled)
__device__ __half g_Woh[256 * 256];          // out_w fp16
__device__ __half g_xh[16 * 256 * 1024];     // x fp16
__device__ __half g_qkvh[16 * 768 * 1024];   // [b][o][p] fp16
__device__ __half g_avh[16 * 256 * 1024];    // [b][c][p] fp16

// ---------------- helpers ----------------
__device__ __forceinline__ float fexp2(float x) {
    float r; asm("ex2.approx.ftz.f32 %0, %1;" : "=f"(r) : "f"(x)); return r;
}
__device__ __forceinline__ void mma_f16(float c[4], const unsigned a[4],
                                        unsigned b0, unsigned b1) {
    asm volatile("mma.sync.aligned.m16n8k16.row.col.f32.f16.f16.f32 "
                 "{%0,%1,%2,%3}, {%4,%5,%6,%7}, {%8,%9}, {%0,%1,%2,%3};"
                 : "+f"(c[0]), "+f"(c[1]), "+f"(c[2]), "+f"(c[3])
                 : "r"(a[0]), "r"(a[1]), "r"(a[2]), "r"(a[3]), "r"(b0), "r"(b1));
}
__device__ __forceinline__ unsigned packh2(float lo, float hi) {
    unsigned d; asm("cvt.rn.f16x2.f32 %0, %1, %2;" : "=r"(d) : "f"(hi), "f"(lo)); return d;
}
__device__ __forceinline__ void cp16(uint32_t dst, const void* src) {
    asm volatile("cp.async.cg.shared.global [%0], [%1], 16;" :: "r"(dst), "l"(src));
}
__device__ __forceinline__ void cp_commit() { asm volatile("cp.async.commit_group;"); }
template<int N> __device__ __forceinline__ void cp_wait() {
    asm volatile("cp.async.wait_group %0;" :: "n"(N));
}
__device__ __forceinline__ void ldsm_x4t(unsigned& d0, unsigned& d1,
                                         unsigned& d2, unsigned& d3, uint32_t addr) {
    asm volatile("ldmatrix.sync.aligned.m8n8.x4.trans.shared.b16 {%0,%1,%2,%3}, [%4];"
                 : "=r"(d0), "=r"(d1), "=r"(d2), "=r"(d3) : "r"(addr));
}

// ---------------- kernel A: fold BN (+softmax scale for Q rows) into QKV weights ----------------
__global__ void fold_k(const float* __restrict__ qkv_w, const float* __restrict__ qkv_b,
                       const float* __restrict__ gamma, const float* __restrict__ beta,
                       const float* __restrict__ mean,  const float* __restrict__ var) {
    int o = blockIdx.x;
    int c = threadIdx.x;
    float sc = gamma[c] * rsqrtf(var[c] + EPSV);
    float sh = beta[c] - mean[c] * sc;
    float w = qkv_w[o * 256 + c];
    float qsc = ((o % 192) < 64) ? QSCALE : 1.f;
    g_Wh[o * 256 + c] = __float2half(w * sc * qsc);
    float part = w * sh;
    __shared__ float red[8];
    #pragma unroll
    for (int m = 16; m > 0; m >>= 1) part += __shfl_xor_sync(0xffffffffu, part, m);
    if ((c & 31) == 0) red[c >> 5] = part;
    __syncthreads();
    if (c < 8) {
        float v = red[c];
        #pragma unroll
        for (int m = 4; m > 0; m >>= 1) v += __shfl_xor_sync(0xffu, v, m);
        if (c == 0) g_bp[o] = (qkv_b[o] + v) * qsc;
    }
}

__global__ void convw_k(const float* __restrict__ w) {
    int i = blockIdx.x * 256 + threadIdx.x;
    g_Woh[i] = __float2half(w[i]);
}

__global__ void convx_k(const float* __restrict__ x) {
    int i = blockIdx.x * 256 + threadIdx.x;      // < 1048576 float4s
    float4 v = ((const float4*)x)[i];
    __half2* o = (__half2*)g_xh;
    o[2 * i]     = __floats2half2_rn(v.x, v.y);
    o[2 * i + 1] = __floats2half2_rn(v.z, v.w);
}

// ---------------- unified fp16 GEMM (pipelined, tensor cores) ----------------
// Y[b][o][p] = W[o][:] . X[b][:][p] + bias[o] (+resid).  N=1024, K=256.
#define GH_WS (128 * 40)
#define GH_XS (32 * 136)
#define GH_SMEM_BYTES (2 * (GH_WS + GH_XS) * 2)

__global__ void __launch_bounds__(256, 2) gemm_h(const __half* __restrict__ W,
                                                 const float* __restrict__ bias,
                                                 const __half* __restrict__ X,
                                                 __half* __restrict__ Yh,
                                                 float* __restrict__ Yf,
                                                 const float* __restrict__ resid,
                                                 int M) {
    extern __shared__ __half sgo[];
    __half* Ws[2] = { sgo, sgo + GH_WS };
    __half* Xs[2] = { sgo + 2 * GH_WS, sgo + 2 * GH_WS + GH_XS };
    uint32_t wsb[2], xsb[2];
    wsb[0] = (uint32_t)__cvta_generic_to_shared(Ws[0]);
    wsb[1] = (uint32_t)__cvta_generic_to_shared(Ws[1]);
    xsb[0] = (uint32_t)__cvta_generic_to_shared(Xs[0]);
    xsb[1] = (uint32_t)__cvta_generic_to_shared(Xs[1]);

    int tid = threadIdx.x;
    int w = tid >> 5, lane = tid & 31, r = lane >> 2, ql = lane & 3;
    int wm = w >> 1, wn = w & 1;
    int pbase = blockIdx.x * 128, obase = blockIdx.y * 128, b = blockIdx.z;
    const __half* Xb = X + (size_t)b * 256 * 1024;

    int g = lane >> 3, jj = lane & 7;
    uint32_t x_rp = (uint32_t)((((g & 1) * 8 + jj) * 136 + (g >> 1) * 8) * 2);

    float acc[2][8][4];
    #pragma unroll
    for (int t = 0; t < 2; t++)
        #pragma unroll
        for (int nb = 0; nb < 8; nb++)
            #pragma unroll
            for (int j = 0; j < 4; j++) acc[t][nb][j] = 0.f;

    const int orow = wm * 32, ncol = wn * 64;

    #pragma unroll
    for (int idx = tid; idx < 1024; idx += 256) {
        if (idx < 512) {
            int o = idx >> 2, f8 = idx & 3;
            cp16(wsb[0] + (uint32_t)(o * 40 + f8 * 8) * 2, W + (size_t)(obase + o) * 256 + f8 * 8);
        } else {
            int j = idx - 512;
            int k = j >> 4, f8 = j & 15;
            cp16(xsb[0] + (uint32_t)(k * 136 + f8 * 8) * 2, Xb + (size_t)k * 1024 + pbase + f8 * 8);
        }
    }
    cp_commit();

    for (int it = 0; it < 8; it++) {
        if (it < 7) {
            int nb2 = (it + 1) & 1;
            int kc = (it + 1) * 32;
            #pragma unroll
            for (int idx = tid; idx < 1024; idx += 256) {
                if (idx < 512) {
                    int o = idx >> 2, f8 = idx & 3;
                    cp16(wsb[nb2] + (uint32_t)(o * 40 + f8 * 8) * 2,
                         W + (size_t)(obase + o) * 256 + kc + f8 * 8);
                } else {
                    int j = idx - 512;
                    int k = j >> 4, f8 = j & 15;
                    cp16(xsb[nb2] + (uint32_t)(k * 136 + f8 * 8) * 2,
                         Xb + (size_t)(kc + k) * 1024 + pbase + f8 * 8);
                }
            }
            cp_commit();
            cp_wait<1>();
        } else {
            cp_wait<0>();
        }
        __syncthreads();

        const __half* Wc = Ws[it & 1];
        uint32_t xcur = xsb[it & 1];
        #pragma unroll
        for (int kk = 0; kk < 2; kk++) {
            unsigned a[2][4];
            #pragma unroll
            for (int t = 0; t < 2; t++) {
                int o0 = orow + t * 16 + r;
                a[t][0] = *(const unsigned*)&Wc[o0 * 40 + kk * 16 + 2 * ql];
                a[t][1] = *(const unsigned*)&Wc[(o0 + 8) * 40 + kk * 16 + 2 * ql];
                a[t][2] = *(const unsigned*)&Wc[o0 * 40 + kk * 16 + 2 * ql + 8];
                a[t][3] = *(const unsigned*)&Wc[(o0 + 8) * 40 + kk * 16 + 2 * ql + 8];
            }
            #pragma unroll
            for (int nb2 = 0; nb2 < 8; nb2 += 2) {
                unsigned d0, d1, d2, d3;
                ldsm_x4t(d0, d1, d2, d3,
                         xcur + (uint32_t)((kk * 16 * 136 + ncol + nb2 * 8) * 2) + x_rp);
                mma_f16(acc[0][nb2],     a[0], d0, d1);
                mma_f16(acc[1][nb2],     a[1], d0, d1);
                mma_f16(acc[0][nb2 + 1], a[0], d2, d3);
                mma_f16(acc[1][nb2 + 1], a[1], d2, d3);
            }
        }
        __syncthreads();
    }

    #pragma unroll
    for (int t = 0; t < 2; t++) {
        int o0 = obase + orow + t * 16 + r;
        float bv0 = bias[o0], bv1 = bias[o0 + 8];
        #pragma unroll
        for (int nb = 0; nb < 8; nb++) {
            int col = pbase + ncol + nb * 8 + 2 * ql;
            size_t i0 = ((size_t)b * M + o0) * 1024 + col;
            size_t i1 = ((size_t)b * M + o0 + 8) * 1024 + col;
            if (Yh) {
                *(unsigned*)&Yh[i0] = packh2(acc[t][nb][0] + bv0, acc[t][nb][1] + bv0);
                *(unsigned*)&Yh[i1] = packh2(acc[t][nb][2] + bv1, acc[t][nb][3] + bv1);
            } else {
                float2 r0 = *(const float2*)&resid[i0];
                float2 r1 = *(const float2*)&resid[i1];
                *(float2*)&Yf[i0] = make_float2(acc[t][nb][0] + bv0 + r0.x,
                                                acc[t][nb][1] + bv0 + r0.y);
                *(float2*)&Yf[i1] = make_float2(acc[t][nb][2] + bv1 + r1.x,
                                                acc[t][nb][3] + bv1 + r1.y);
            }
        }
    }
}

// ---------------- flash attention: fp16 mma, 16 q-rows/warp, 2 CTAs/SM ----------------
// q-tile 128, grid (8, 4, 16), block 256 (8 warps).
#define FH_QSTR 136
#define FH_KSTR 72
#define FH_U   (64 * FH_QSTR)
#define FH_KSZ (64 * FH_KSTR)
#define FH_SMEM_BYTES ((FH_U + 4 * FH_KSZ) * 2)

__global__ void __launch_bounds__(256, 2) flash_h(const __half* __restrict__ qkv,
                                                  __half* __restrict__ av) {
    extern __shared__ __half sh[];
    __half* Us = sh;
    __half* Vb[2] = { sh + FH_U + 2 * FH_KSZ, sh + FH_U + 3 * FH_KSZ };
    uint32_t usb = (uint32_t)__cvta_generic_to_shared(Us);
    uint32_t ksb[2], vsb[2];
    ksb[0] = (uint32_t)__cvta_generic_to_shared(sh + FH_U);
    ksb[1] = (uint32_t)__cvta_generic_to_shared(sh + FH_U + FH_KSZ);
    vsb[0] = (uint32_t)__cvta_generic_to_shared(Vb[0]);
    vsb[1] = (uint32_t)__cvta_generic_to_shared(Vb[1]);

    int tid = threadIdx.x;
    int w = tid >> 5, lane = tid & 31, r = lane >> 2, ql = lane & 3;
    int qb = blockIdx.x * 128;
    int h  = blockIdx.y;
    int b  = blockIdx.z;

    const size_t hb = ((size_t)b * 768 + (size_t)h * 192) * 1024;
    const __half* Qg = qkv + hb;
    const __half* Kg = qkv + hb + 64 * 1024;
    const __half* Vg = qkv + hb + 128 * 1024;

    // stage Q [c][q] (64 x 128 halves)
    #pragma unroll
    for (int idx = tid; idx < 1024; idx += 256) {
        int c = idx >> 4, f8 = idx & 15;
        cp16(usb + (uint32_t)(c * FH_QSTR + f8 * 8) * 2, Qg + (size_t)c * 1024 + qb + f8 * 8);
    }
    cp_commit();
    // K/V tile 0
    #pragma unroll
    for (int idx = tid; idx < 1024; idx += 256) {
        if (idx < 512) {
            int c = idx >> 3, f8 = idx & 7;
            cp16(ksb[0] + (uint32_t)(c * FH_KSTR + f8 * 8) * 2, Kg + (size_t)c * 1024 + f8 * 8);
        } else {
            int j = idx - 512;
            int c = j >> 3, f8 = j & 7;
            cp16(vsb[0] + (uint32_t)(c * FH_KSTR + f8 * 8) * 2, Vg + (size_t)c * 1024 + f8 * 8);
        }
    }
    cp_commit();
    cp_wait<1>();
    __syncthreads();

    // Q fragments (one-time)
    const int qrow = w * 16;
    const unsigned short* Uss = (const unsigned short*)Us;
    unsigned qf[4][4];
    #pragma unroll
    for (int kk = 0; kk < 4; kk++) {
        int q0 = qrow + r;
        int c0 = kk * 16 + 2 * ql;
        qf[kk][0] = (unsigned)Uss[c0 * FH_QSTR + q0]           | ((unsigned)Uss[(c0 + 1) * FH_QSTR + q0] << 16);
        qf[kk][1] = (unsigned)Uss[c0 * FH_QSTR + q0 + 8]       | ((unsigned)Uss[(c0 + 1) * FH_QSTR + q0 + 8] << 16);
        qf[kk][2] = (unsigned)Uss[(c0 + 8) * FH_QSTR + q0]     | ((unsigned)Uss[(c0 + 9) * FH_QSTR + q0] << 16);
        qf[kk][3] = (unsigned)Uss[(c0 + 8) * FH_QSTR + q0 + 8] | ((unsigned)Uss[(c0 + 9) * FH_QSTR + q0 + 8] << 16);
    }

    int g = lane >> 3, jj = lane & 7;
    uint32_t k_rp = (uint32_t)((((g & 1) * 8 + jj) * FH_KSTR + (g >> 1) * 8) * 2);

    float m0 = -1e30f, m1 = -1e30f, l0 = 0.f, l1 = 0.f;
    float O[8][4];
    #pragma unroll
    for (int nb = 0; nb < 8; nb++)
        #pragma unroll
        for (int j = 0; j < 4; j++) O[nb][j] = 0.f;

    for (int kt = 0; kt < 16; kt++) {
        if (kt < 15) {
            int nb2 = (kt + 1) & 1;
            int kbase = (kt + 1) * 64;
            #pragma unroll
            for (int idx = tid; idx < 1024; idx += 256) {
                if (idx < 512) {
                    int c = idx >> 3, f8 = idx & 7;
                    cp16(ksb[nb2] + (uint32_t)(c * FH_KSTR + f8 * 8) * 2,
                         Kg + (size_t)c * 1024 + kbase + f8 * 8);
                } else {
                    int j = idx - 512;
                    int c = j >> 3, f8 = j & 7;
                    cp16(vsb[nb2] + (uint32_t)(c * FH_KSTR + f8 * 8) * 2,
                         Vg + (size_t)c * 1024 + kbase + f8 * 8);
                }
            }
            cp_commit();
            cp_wait<1>();
        } else {
            cp_wait<0>();
        }
        __syncthreads();

        uint32_t kcur = ksb[kt & 1];
        const __half* Vc = Vb[kt & 1];

        // ---- S = Q K^T (scale pre-folded into Q) ----
        float S[8][4];
        #pragma unroll
        for (int nb = 0; nb < 8; nb++)
            #pragma unroll
            for (int j = 0; j < 4; j++) S[nb][j] = 0.f;

        #pragma unroll
        for (int kk = 0; kk < 4; kk++) {
            #pragma unroll
            for (int nb2 = 0; nb2 < 8; nb2 += 2) {
                unsigned d0, d1, d2, d3;
                ldsm_x4t(d0, d1, d2, d3,
                         kcur + (uint32_t)((kk * 16 * FH_KSTR + nb2 * 8) * 2) + k_rp);
                mma_f16(S[nb2],     qf[kk], d0, d1);
                mma_f16(S[nb2 + 1], qf[kk], d2, d3);
            }
        }

        // ---- online softmax (exp2 direct) ----
        float mx0 = -1e30f, mx1 = -1e30f;
        #pragma unroll
        for (int nb = 0; nb < 8; nb++) {
            mx0 = fmaxf(mx0, fmaxf(S[nb][0], S[nb][1]));
            mx1 = fmaxf(mx1, fmaxf(S[nb][2], S[nb][3]));
        }
        mx0 = fmaxf(mx0, __shfl_xor_sync(0xffffffffu, mx0, 1));
        mx0 = fmaxf(mx0, __shfl_xor_sync(0xffffffffu, mx0, 2));
        mx1 = fmaxf(mx1, __shfl_xor_sync(0xffffffffu, mx1, 1));
        mx1 = fmaxf(mx1, __shfl_xor_sync(0xffffffffu, mx1, 2));

        float mn0 = fmaxf(m0, mx0), mn1 = fmaxf(m1, mx1);
        float al0 = fexp2(m0 - mn0), al1 = fexp2(m1 - mn1);
        m0 = mn0; m1 = mn1;

        float rs0 = 0.f, rs1 = 0.f;
        #pragma unroll
        for (int nb = 0; nb < 8; nb++) {
            S[nb][0] = fexp2(S[nb][0] - mn0);
            S[nb][1] = fexp2(S[nb][1] - mn0);
            S[nb][2] = fexp2(S[nb][2] - mn1);
            S[nb][3] = fexp2(S[nb][3] - mn1);
            rs0 += S[nb][0] + S[nb][1];
            rs1 += S[nb][2] + S[nb][3];
        }
        rs0 += __shfl_xor_sync(0xffffffffu, rs0, 1);
        rs0 += __shfl_xor_sync(0xffffffffu, rs0, 2);
        rs1 += __shfl_xor_sync(0xffffffffu, rs1, 1);
        rs1 += __shfl_xor_sync(0xffffffffu, rs1, 2);
        l0 = l0 * al0 + rs0;
        l1 = l1 * al1 + rs1;

        #pragma unroll
        for (int nb = 0; nb < 8; nb++) {
            O[nb][0] *= al0; O[nb][1] *= al0;
            O[nb][2] *= al1; O[nb][3] *= al1;
        }

        // ---- pack P to fp16 A-frags ----
        unsigned pa[4][4];
        #pragma unroll
        for (int kk = 0; kk < 4; kk++) {
            pa[kk][0] = packh2(S[2 * kk][0],     S[2 * kk][1]);
            pa[kk][1] = packh2(S[2 * kk][2],     S[2 * kk][3]);
            pa[kk][2] = packh2(S[2 * kk + 1][0], S[2 * kk + 1][1]);
            pa[kk][3] = packh2(S[2 * kk + 1][2], S[2 * kk + 1][3]);
        }

        // ---- O += P V ----
        #pragma unroll
        for (int kk = 0; kk < 4; kk++) {
            #pragma unroll
            for (int nb = 0; nb < 8; nb++) {
                unsigned b0 = *(const unsigned*)&Vc[(nb * 8 + r) * FH_KSTR + kk * 16 + 2 * ql];
                unsigned b1 = *(const unsigned*)&Vc[(nb * 8 + r) * FH_KSTR + kk * 16 + 2 * ql + 8];
                mma_f16(O[nb], pa[kk], b0, b1);
            }
        }
        __syncthreads();
    }

    // ---- finalize: stage fp16 [c][q], coalesced store ----
    unsigned short* Uw = (unsigned short*)Us;
    float inv0 = 1.f / l0, inv1 = 1.f / l1;
    int q0 = qrow + r;
    #pragma unroll
    for (int nb = 0; nb < 8; nb++) {
        int c = nb * 8 + 2 * ql;
        Uw[c * FH_QSTR + q0]           = __half_as_ushort(__float2half(O[nb][0] * inv0));
        Uw[(c + 1) * FH_QSTR + q0]     = __half_as_ushort(__float2half(O[nb][1] * inv0));
        Uw[c * FH_QSTR + q0 + 8]       = __half_as_ushort(__float2half(O[nb][2] * inv1));
        Uw[(c + 1) * FH_QSTR + q0 + 8] = __half_as_ushort(__float2half(O[nb][3] * inv1));
    }
    __syncthreads();

    size_t ob = ((size_t)b * 256 + (size_t)h * 64) * 1024 + qb;
    for (int idx = tid; idx < 64 * 64; idx += 256) {
        int c = idx >> 6, wd = idx & 63;
        *(unsigned*)&av[ob + (size_t)c * 1024 + wd * 2] = ((unsigned*)Us)[c * (FH_QSTR / 2) + wd];
    }
}

// ---------------- launcher ----------------
extern "C" void kernel_launch(void* const* d_in, const int* in_sizes, int n_in,
                              void* d_out, int out_size) {
    const float* x      = (const float*)d_in[0];
    const float* gamma  = (const float*)d_in[1];
    const float* beta   = (const float*)d_in[2];
    const float* rmean  = (const float*)d_in[3];
    const float* rvar   = (const float*)d_in[4];
    const float* qkv_w  = (const float*)d_in[5];
    const float* qkv_b  = (const float*)d_in[6];
    const float* out_w  = (const float*)d_in[7];
    const float* out_b  = (const float*)d_in[8];

    float* bp;
    __half *Wh, *Woh, *xh, *qkvh, *avh;
    cudaGetSymbolAddress((void**)&Wh,   g_Wh);
    cudaGetSymbolAddress((void**)&bp,   g_bp);
    cudaGetSymbolAddress((void**)&Woh,  g_Woh);
    cudaGetSymbolAddress((void**)&xh,   g_xh);
    cudaGetSymbolAddress((void**)&qkvh, g_qkvh);
    cudaGetSymbolAddress((void**)&avh,  g_avh);

    cudaFuncSetAttribute(gemm_h,  cudaFuncAttributeMaxDynamicSharedMemorySize, GH_SMEM_BYTES);
    cudaFuncSetAttribute(flash_h, cudaFuncAttributeMaxDynamicSharedMemorySize, FH_SMEM_BYTES);

    fold_k<<<768, 256>>>(qkv_w, qkv_b, gamma, beta, rmean, rvar);
    convw_k<<<256, 256>>>(out_w);
    convx_k<<<4096, 256>>>(x);
    gemm_h<<<dim3(8, 6, 16), 256, GH_SMEM_BYTES>>>(Wh, bp, xh, qkvh, nullptr, nullptr, 768);
    flash_h<<<dim3(8, 4, 16), 256, FH_SMEM_BYTES>>>(qkvh, avh);
    gemm_h<<<dim3(8, 2, 16), 256, GH_SMEM_BYTES>>>(Woh, out_b, avh, nullptr, (float*)d_out, x, 256);
}

// round 7
// speedup vs baseline: 8.9692x; 1.2084x over previous
#include <cuda_runtime.h>
#include <cuda_fp16.h>
#include <cstdint>

#define EPSV 1e-5f
#define QSCALE (0.0625f * 1.44269504088896340736f)   // 1/sqrt(256) * log2(e)

// ---------------- scratch ----------------
__device__ __half g_Wh[768 * 256];           // BN+scale folded QKV weight (fp16)
__device__ float  g_bp[768];                 // folded QKV bias (fp32, Q rows scaled)
__device__ __half g_Woh[256 * 256];          // out_w fp16
__device__ __half g_xh[16 * 256 * 1024];     // x fp16
__device__ __half g_qkvh[16 * 768 * 1024];   // [b][o][p] fp16
__device__ __half g_avh[16 * 256 * 1024];    // [b][c][p] fp16

// ---------------- helpers ----------------
__device__ __forceinline__ float fexp2(float x) {
    float r; asm("ex2.approx.ftz.f32 %0, %1;" : "=f"(r) : "f"(x)); return r;
}
__device__ __forceinline__ void mma_f16(float c[4], const unsigned a[4],
                                        unsigned b0, unsigned b1) {
    asm volatile("mma.sync.aligned.m16n8k16.row.col.f32.f16.f16.f32 "
                 "{%0,%1,%2,%3}, {%4,%5,%6,%7}, {%8,%9}, {%0,%1,%2,%3};"
                 : "+f"(c[0]), "+f"(c[1]), "+f"(c[2]), "+f"(c[3])
                 : "r"(a[0]), "r"(a[1]), "r"(a[2]), "r"(a[3]), "r"(b0), "r"(b1));
}
__device__ __forceinline__ unsigned packh2(float lo, float hi) {
    unsigned d; asm("cvt.rn.f16x2.f32 %0, %1, %2;" : "=r"(d) : "f"(hi), "f"(lo)); return d;
}
__device__ __forceinline__ void cp16(uint32_t dst, const void* src) {
    asm volatile("cp.async.cg.shared.global [%0], [%1], 16;" :: "r"(dst), "l"(src));
}
__device__ __forceinline__ void cp_commit() { asm volatile("cp.async.commit_group;"); }
template<int N> __device__ __forceinline__ void cp_wait() {
    asm volatile("cp.async.wait_group %0;" :: "n"(N));
}
__device__ __forceinline__ void ldsm_x4t(unsigned& d0, unsigned& d1,
                                         unsigned& d2, unsigned& d3, uint32_t addr) {
    asm volatile("ldmatrix.sync.aligned.m8n8.x4.trans.shared.b16 {%0,%1,%2,%3}, [%4];"
                 : "=r"(d0), "=r"(d1), "=r"(d2), "=r"(d3) : "r"(addr));
}
__device__ __forceinline__ void ldsm_x4(unsigned& d0, unsigned& d1,
                                        unsigned& d2, unsigned& d3, uint32_t addr) {
    asm volatile("ldmatrix.sync.aligned.m8n8.x4.shared.b16 {%0,%1,%2,%3}, [%4];"
                 : "=r"(d0), "=r"(d1), "=r"(d2), "=r"(d3) : "r"(addr));
}

// ---------------- kernel A: fold BN (+softmax scale for Q rows) into QKV weights ----------------
__global__ void fold_k(const float* __restrict__ qkv_w, const float* __restrict__ qkv_b,
                       const float* __restrict__ gamma, const float* __restrict__ beta,
                       const float* __restrict__ mean,  const float* __restrict__ var) {
    int o = blockIdx.x;
    int c = threadIdx.x;
    float sc = gamma[c] * rsqrtf(var[c] + EPSV);
    float sh = beta[c] - mean[c] * sc;
    float w = qkv_w[o * 256 + c];
    float qsc = ((o % 192) < 64) ? QSCALE : 1.f;
    g_Wh[o * 256 + c] = __float2half(w * sc * qsc);
    float part = w * sh;
    __shared__ float red[8];
    #pragma unroll
    for (int m = 16; m > 0; m >>= 1) part += __shfl_xor_sync(0xffffffffu, part, m);
    if ((c & 31) == 0) red[c >> 5] = part;
    __syncthreads();
    if (c < 8) {
        float v = red[c];
        #pragma unroll
        for (int m = 4; m > 0; m >>= 1) v += __shfl_xor_sync(0xffu, v, m);
        if (c == 0) g_bp[o] = (qkv_b[o] + v) * qsc;
    }
}

__global__ void convw_k(const float* __restrict__ w) {
    int i = blockIdx.x * 256 + threadIdx.x;
    g_Woh[i] = __float2half(w[i]);
}

__global__ void convx_k(const float* __restrict__ x) {
    int i = blockIdx.x * 256 + threadIdx.x;
    float4 v = ((const float4*)x)[i];
    __half2* o = (__half2*)g_xh;
    o[2 * i]     = __floats2half2_rn(v.x, v.y);
    o[2 * i + 1] = __floats2half2_rn(v.z, v.w);
}

// ---------------- unified fp16 GEMM: 3-stage cp.async, 1 sync/iter ----------------
// Y[b][o][p] = W[o][:] . X[b][:][p] + bias[o] (+resid).  N=1024, K=256.
#define GH_WS (128 * 40)
#define GH_XS (32 * 136)
#define GH_STG (GH_WS + GH_XS)
#define GH_SMEM_BYTES (3 * GH_STG * 2)

__device__ __forceinline__ void gh_load(uint32_t sb, const __half* W, const __half* Xb,
                                        int obase, int pbase, int kc, int tid) {
    #pragma unroll
    for (int idx = tid; idx < 1024; idx += 256) {
        if (idx < 512) {
            int o = idx >> 2, f8 = idx & 3;
            cp16(sb + (uint32_t)(o * 40 + f8 * 8) * 2, W + (size_t)(obase + o) * 256 + kc + f8 * 8);
        } else {
            int j = idx - 512;
            int k = j >> 4, f8 = j & 15;
            cp16(sb + (uint32_t)(GH_WS + k * 136 + f8 * 8) * 2,
                 Xb + (size_t)(kc + k) * 1024 + pbase + f8 * 8);
        }
    }
}

__global__ void __launch_bounds__(256, 2) gemm_h(const __half* __restrict__ W,
                                                 const float* __restrict__ bias,
                                                 const __half* __restrict__ X,
                                                 __half* __restrict__ Yh,
                                                 float* __restrict__ Yf,
                                                 const float* __restrict__ resid,
                                                 int M) {
    extern __shared__ __half sgo[];
    uint32_t sb0 = (uint32_t)__cvta_generic_to_shared(sgo);

    int tid = threadIdx.x;
    int w = tid >> 5, lane = tid & 31, r = lane >> 2, ql = lane & 3;
    int wm = w >> 1, wn = w & 1;
    int pbase = blockIdx.x * 128, obase = blockIdx.y * 128, b = blockIdx.z;
    const __half* Xb = X + (size_t)b * 256 * 1024;

    int g = lane >> 3, jj = lane & 7;
    uint32_t x_rp = (uint32_t)((((g & 1) * 8 + jj) * 136 + (g >> 1) * 8) * 2);
    // W ldmatrix lane offset: row = lane&15, col-half = lane>>4
    uint32_t w_rp = (uint32_t)(((lane & 15) * 40 + (lane >> 4) * 8) * 2);

    float acc[2][8][4];
    #pragma unroll
    for (int t = 0; t < 2; t++)
        #pragma unroll
        for (int nb = 0; nb < 8; nb++)
            #pragma unroll
            for (int j = 0; j < 4; j++) acc[t][nb][j] = 0.f;

    const int orow = wm * 32, ncol = wn * 64;

    gh_load(sb0, W, Xb, obase, pbase, 0, tid);  cp_commit();
    gh_load(sb0 + GH_STG * 2, W, Xb, obase, pbase, 32, tid);  cp_commit();

    for (int it = 0; it < 8; it++) {
        cp_wait<1>();
        __syncthreads();

        uint32_t sbc = sb0 + (uint32_t)(it % 3) * GH_STG * 2;
        #pragma unroll
        for (int kk = 0; kk < 2; kk++) {
            unsigned a[2][4];
            #pragma unroll
            for (int t = 0; t < 2; t++)
                ldsm_x4(a[t][0], a[t][1], a[t][2], a[t][3],
                        sbc + (uint32_t)(((orow + t * 16) * 40 + kk * 16) * 2) + w_rp);
            #pragma unroll
            for (int nb2 = 0; nb2 < 8; nb2 += 2) {
                unsigned d0, d1, d2, d3;
                ldsm_x4t(d0, d1, d2, d3,
                         sbc + (uint32_t)((GH_WS + kk * 16 * 136 + ncol + nb2 * 8) * 2) + x_rp);
                mma_f16(acc[0][nb2],     a[0], d0, d1);
                mma_f16(acc[1][nb2],     a[1], d0, d1);
                mma_f16(acc[0][nb2 + 1], a[0], d2, d3);
                mma_f16(acc[1][nb2 + 1], a[1], d2, d3);
            }
        }

        if (it + 2 < 8)
            gh_load(sb0 + (uint32_t)((it + 2) % 3) * GH_STG * 2, W, Xb,
                    obase, pbase, (it + 2) * 32, tid);
        cp_commit();
    }

    #pragma unroll
    for (int t = 0; t < 2; t++) {
        int o0 = obase + orow + t * 16 + r;
        float bv0 = bias[o0], bv1 = bias[o0 + 8];
        #pragma unroll
        for (int nb = 0; nb < 8; nb++) {
            int col = pbase + ncol + nb * 8 + 2 * ql;
            size_t i0 = ((size_t)b * M + o0) * 1024 + col;
            size_t i1 = ((size_t)b * M + o0 + 8) * 1024 + col;
            if (Yh) {
                *(unsigned*)&Yh[i0] = packh2(acc[t][nb][0] + bv0, acc[t][nb][1] + bv0);
                *(unsigned*)&Yh[i1] = packh2(acc[t][nb][2] + bv1, acc[t][nb][3] + bv1);
            } else {
                float2 r0 = *(const float2*)&resid[i0];
                float2 r1 = *(const float2*)&resid[i1];
                *(float2*)&Yf[i0] = make_float2(acc[t][nb][0] + bv0 + r0.x,
                                                acc[t][nb][1] + bv0 + r0.y);
                *(float2*)&Yf[i1] = make_float2(acc[t][nb][2] + bv1 + r1.x,
                                                acc[t][nb][3] + bv1 + r1.y);
            }
        }
    }
}

// ---------------- flash attention: fp16 mma, static softmax, 3-stage pipeline ----------------
// q-tile 128, grid (8, 4, 16), block 256 (8 warps, 16 q-rows/warp), 2 CTAs/SM.
#define FH_QSTR 136
#define FH_KSTR 72
#define FH_U   (64 * FH_QSTR)
#define FH_KV  (64 * FH_KSTR)
#define FH_SMEM_BYTES ((FH_U + 6 * FH_KV) * 2)

__global__ void __launch_bounds__(256, 2) flash_h(const __half* __restrict__ qkv,
                                                  __half* __restrict__ av) {
    extern __shared__ __half sh[];
    __half* Us = sh;
    uint32_t usb = (uint32_t)__cvta_generic_to_shared(Us);

    int tid = threadIdx.x;
    int w = tid >> 5, lane = tid & 31, r = lane >> 2, ql = lane & 3;
    int qb = blockIdx.x * 128;
    int h  = blockIdx.y;
    int b  = blockIdx.z;

    const size_t hb = ((size_t)b * 768 + (size_t)h * 192) * 1024;
    const __half* Qg = qkv + hb;
    const __half* Kg = qkv + hb + 64 * 1024;
    const __half* Vg = qkv + hb + 128 * 1024;

    // stage-s K/V base byte addresses
    auto kbuf = [&](int s) { return usb + (uint32_t)(FH_U + s * 2 * FH_KV) * 2; };
    auto vbuf = [&](int s) { return usb + (uint32_t)(FH_U + s * 2 * FH_KV + FH_KV) * 2; };

    auto load_kv = [&](int s, int kbase) {
        uint32_t kb = kbuf(s), vb = vbuf(s);
        #pragma unroll
        for (int idx = tid; idx < 1024; idx += 256) {
            if (idx < 512) {
                int c = idx >> 3, f8 = idx & 7;
                cp16(kb + (uint32_t)(c * FH_KSTR + f8 * 8) * 2,
                     Kg + (size_t)c * 1024 + kbase + f8 * 8);
            } else {
                int j = idx - 512;
                int c = j >> 3, f8 = j & 7;
                cp16(vb + (uint32_t)(c * FH_KSTR + f8 * 8) * 2,
                     Vg + (size_t)c * 1024 + kbase + f8 * 8);
            }
        }
    };

    // prologue: Q (g0), KV0 (g1), KV1 (g2)
    #pragma unroll
    for (int idx = tid; idx < 1024; idx += 256) {
        int c = idx >> 4, f8 = idx & 15;
        cp16(usb + (uint32_t)(c * FH_QSTR + f8 * 8) * 2, Qg + (size_t)c * 1024 + qb + f8 * 8);
    }
    cp_commit();
    load_kv(0, 0);   cp_commit();
    load_kv(1, 64);  cp_commit();

    cp_wait<2>();
    __syncthreads();

    // Q fragments (one-time)
    const int qrow = w * 16;
    const unsigned short* Uss = (const unsigned short*)Us;
    unsigned qf[4][4];
    #pragma unroll
    for (int kk = 0; kk < 4; kk++) {
        int q0 = qrow + r;
        int c0 = kk * 16 + 2 * ql;
        qf[kk][0] = (unsigned)Uss[c0 * FH_QSTR + q0]           | ((unsigned)Uss[(c0 + 1) * FH_QSTR + q0] << 16);
        qf[kk][1] = (unsigned)Uss[c0 * FH_QSTR + q0 + 8]       | ((unsigned)Uss[(c0 + 1) * FH_QSTR + q0 + 8] << 16);
        qf[kk][2] = (unsigned)Uss[(c0 + 8) * FH_QSTR + q0]     | ((unsigned)Uss[(c0 + 9) * FH_QSTR + q0] << 16);
        qf[kk][3] = (unsigned)Uss[(c0 + 8) * FH_QSTR + q0 + 8] | ((unsigned)Uss[(c0 + 9) * FH_QSTR + q0 + 8] << 16);
    }

    int g = lane >> 3, jj = lane & 7;
    uint32_t k_rp = (uint32_t)((((g & 1) * 8 + jj) * FH_KSTR + (g >> 1) * 8) * 2);

    float l0 = 0.f, l1 = 0.f;
    float O[8][4];
    #pragma unroll
    for (int nb = 0; nb < 8; nb++)
        #pragma unroll
        for (int j = 0; j < 4; j++) O[nb][j] = 0.f;

    for (int kt = 0; kt < 16; kt++) {
        cp_wait<1>();
        __syncthreads();

        int s = kt % 3;
        uint32_t kcur = kbuf(s);
        const __half* Vc = (const __half*)(sh + FH_U + s * 2 * FH_KV + FH_KV);

        // ---- S = Q K^T (softmax scale pre-folded into Q weights, exp2 base) ----
        float S[8][4];
        #pragma unroll
        for (int nb = 0; nb < 8; nb++)
            #pragma unroll
            for (int j = 0; j < 4; j++) S[nb][j] = 0.f;

        #pragma unroll
        for (int kk = 0; kk < 4; kk++) {
            #pragma unroll
            for (int nb2 = 0; nb2 < 8; nb2 += 2) {
                unsigned d0, d1, d2, d3;
                ldsm_x4t(d0, d1, d2, d3,
                         kcur + (uint32_t)((kk * 16 * FH_KSTR + nb2 * 8) * 2) + k_rp);
                mma_f16(S[nb2],     qf[kk], d0, d1);
                mma_f16(S[nb2 + 1], qf[kk], d2, d3);
            }
        }

        // ---- static softmax: P = exp2(S), accumulate row sums in registers ----
        #pragma unroll
        for (int nb = 0; nb < 8; nb++) {
            S[nb][0] = fexp2(S[nb][0]);
            S[nb][1] = fexp2(S[nb][1]);
            S[nb][2] = fexp2(S[nb][2]);
            S[nb][3] = fexp2(S[nb][3]);
            l0 += S[nb][0] + S[nb][1];
            l1 += S[nb][2] + S[nb][3];
        }

        // ---- pack P to fp16 A-frags ----
        unsigned pa[4][4];
        #pragma unroll
        for (int kk = 0; kk < 4; kk++) {
            pa[kk][0] = packh2(S[2 * kk][0],     S[2 * kk][1]);
            pa[kk][1] = packh2(S[2 * kk][2],     S[2 * kk][3]);
            pa[kk][2] = packh2(S[2 * kk + 1][0], S[2 * kk + 1][1]);
            pa[kk][3] = packh2(S[2 * kk + 1][2], S[2 * kk + 1][3]);
        }

        // ---- O += P V ----
        #pragma unroll
        for (int kk = 0; kk < 4; kk++) {
            #pragma unroll
            for (int nb = 0; nb < 8; nb++) {
                unsigned b0 = *(const unsigned*)&Vc[(nb * 8 + r) * FH_KSTR + kk * 16 + 2 * ql];
                unsigned b1 = *(const unsigned*)&Vc[(nb * 8 + r) * FH_KSTR + kk * 16 + 2 * ql + 8];
                mma_f16(O[nb], pa[kk], b0, b1);
            }
        }

        if (kt + 2 < 16) load_kv((kt + 2) % 3, (kt + 2) * 64);
        cp_commit();
    }

    // ---- finalize: single row-sum reduce, stage fp16 [c][q], coalesced store ----
    l0 += __shfl_xor_sync(0xffffffffu, l0, 1);
    l0 += __shfl_xor_sync(0xffffffffu, l0, 2);
    l1 += __shfl_xor_sync(0xffffffffu, l1, 1);
    l1 += __shfl_xor_sync(0xffffffffu, l1, 2);
    float inv0 = 1.f / l0, inv1 = 1.f / l1;

    unsigned short* Uw = (unsigned short*)Us;
    int q0 = qrow + r;
    #pragma unroll
    for (int nb = 0; nb < 8; nb++) {
        int c = nb * 8 + 2 * ql;
        Uw[c * FH_QSTR + q0]           = __half_as_ushort(__float2half(O[nb][0] * inv0));
        Uw[(c + 1) * FH_QSTR + q0]     = __half_as_ushort(__float2half(O[nb][1] * inv0));
        Uw[c * FH_QSTR + q0 + 8]       = __half_as_ushort(__float2half(O[nb][2] * inv1));
        Uw[(c + 1) * FH_QSTR + q0 + 8] = __half_as_ushort(__float2half(O[nb][3] * inv1));
    }
    __syncthreads();

    size_t ob = ((size_t)b * 256 + (size_t)h * 64) * 1024 + qb;
    for (int idx = tid; idx < 64 * 64; idx += 256) {
        int c = idx >> 6, wd = idx & 63;
        *(unsigned*)&av[ob + (size_t)c * 1024 + wd * 2] = ((unsigned*)Us)[c * (FH_QSTR / 2) + wd];
    }
}

// ---------------- launcher ----------------
extern "C" void kernel_launch(void* const* d_in, const int* in_sizes, int n_in,
                              void* d_out, int out_size) {
    const float* x      = (const float*)d_in[0];
    const float* gamma  = (const float*)d_in[1];
    const float* beta   = (const float*)d_in[2];
    const float* rmean  = (const float*)d_in[3];
    const float* rvar   = (const float*)d_in[4];
    const float* qkv_w  = (const float*)d_in[5];
    const float* qkv_b  = (const float*)d_in[6];
    const float* out_w  = (const float*)d_in[7];
    const float* out_b  = (const float*)d_in[8];

    float* bp;
    __half *Wh, *Woh, *xh, *qkvh, *avh;
    cudaGetSymbolAddress((void**)&Wh,   g_Wh);
    cudaGetSymbolAddress((void**)&bp,   g_bp);
    cudaGetSymbolAddress((void**)&Woh,  g_Woh);
    cudaGetSymbolAddress((void**)&xh,   g_xh);
    cudaGetSymbolAddress((void**)&qkvh, g_qkvh);
    cudaGetSymbolAddress((void**)&avh,  g_avh);

    cudaFuncSetAttribute(gemm_h,  cudaFuncAttributeMaxDynamicSharedMemorySize, GH_SMEM_BYTES);
    cudaFuncSetAttribute(flash_h, cudaFuncAttributeMaxDynamicSharedMemorySize, FH_SMEM_BYTES);

    fold_k<<<768, 256>>>(qkv_w, qkv_b, gamma, beta, rmean, rvar);
    convw_k<<<256, 256>>>(out_w);
    convx_k<<<4096, 256>>>(x);
    gemm_h<<<dim3(8, 6, 16), 256, GH_SMEM_BYTES>>>(Wh, bp, xh, qkvh, nullptr, nullptr, 768);
    flash_h<<<dim3(8, 4, 16), 256, FH_SMEM_BYTES>>>(qkvh, avh);
    gemm_h<<<dim3(8, 2, 16), 256, GH_SMEM_BYTES>>>(Woh, out_b, avh, nullptr, (float*)d_out, x, 256);
}